// round 1
// baseline (speedup 1.0000x reference)
#include <cuda_runtime.h>
#include <cstdint>

// Problem constants
#define B_  8
#define T_  1024
#define C_  768
#define H_  12
#define HS_ 64
#define M_  8192   // B*T

// Scratch (device globals; runtime allocation is forbidden)
__device__ float g_Q[B_*H_*T_*HS_];
__device__ float g_K[B_*H_*T_*HS_];
__device__ float g_V[B_*H_*T_*HS_];
__device__ float g_Y[(size_t)M_*C_];

__device__ __forceinline__ void cpa16(uint32_t s, const float* g){
    asm volatile("cp.async.cg.shared.global [%0], [%1], 16;" :: "r"(s), "l"(g));
}

// ---------------------------------------------------------------------------
// SGEMM: C[M,N] = A[M,K] @ B[K,N] + bias[N]
// MODE 0: A = g_Y (param ignored), store to Cout (d_out)
// MODE 1: A = x, scatter epilogue into g_Q/g_K/g_V with [B,H,T,hs] layout
// 128x128 block, BK=16, 256 threads, 8x8 per thread, 2-stage cp.async pipeline
// ---------------------------------------------------------------------------
template<int MODE>
__global__ __launch_bounds__(256, 2)
void sgemm_kernel(const float* __restrict__ A, const float* __restrict__ Bm,
                  const float* __restrict__ bias, float* __restrict__ Cout,
                  int M, int N, int K)
{
    __shared__ float As[2][128][16];
    __shared__ float Bs[2][16][128];

    const float* Ap = (MODE == 0) ? g_Y : A;

    const int tid = threadIdx.x;
    const int ty  = tid >> 4;     // 0..15 (row group)
    const int tx  = tid & 15;     // 0..15 (col group)
    const int br  = blockIdx.y;
    const int bc  = blockIdx.x;

    // load mapping (coalesced 16B chunks)
    const int a_row = tid >> 2;          // 0..63
    const int a_q   = (tid & 3) << 2;    // 0,4,8,12
    const int b_k   = tid >> 5;          // 0..7
    const int b_c   = (tid & 31) << 2;   // 0..124

    const float* Abase = Ap + (size_t)(br*128 + a_row) * K + a_q;
    const float* Bbase = Bm + (size_t)b_k * N + bc*128 + b_c;

    const uint32_t sA = (uint32_t)__cvta_generic_to_shared(&As[0][0][0]);
    const uint32_t sB = (uint32_t)__cvta_generic_to_shared(&Bs[0][0][0]);
    const uint32_t sAw0 = sA + (uint32_t)(a_row*16 + a_q)*4;
    const uint32_t sAw1 = sA + (uint32_t)((a_row+64)*16 + a_q)*4;
    const uint32_t sBw0 = sB + (uint32_t)(b_k*128 + b_c)*4;
    const uint32_t sBw1 = sB + (uint32_t)((b_k+8)*128 + b_c)*4;

    const int nk = K >> 4;

    float acc[8][8];
#pragma unroll
    for (int i = 0; i < 8; i++)
#pragma unroll
        for (int j = 0; j < 8; j++) acc[i][j] = 0.f;

#define LOADSTAGE(kb, buf) do {                                   \
        const float* ap_ = Abase + (size_t)(kb)*16;               \
        cpa16(sAw0 + (buf)*8192u, ap_);                           \
        cpa16(sAw1 + (buf)*8192u, ap_ + (size_t)64*K);            \
        const float* bp_ = Bbase + (size_t)(kb)*16*N;             \
        cpa16(sBw0 + (buf)*8192u, bp_);                           \
        cpa16(sBw1 + (buf)*8192u, bp_ + (size_t)8*N);             \
        asm volatile("cp.async.commit_group;");                   \
    } while (0)

    LOADSTAGE(0, 0);
    asm volatile("cp.async.wait_group 0;");
    __syncthreads();

    for (int kb = 0; kb < nk; kb++){
        const int cur = kb & 1;
        if (kb + 1 < nk) LOADSTAGE(kb + 1, cur ^ 1);

#pragma unroll
        for (int k = 0; k < 16; k++){
            float a[8];
#pragma unroll
            for (int i = 0; i < 8; i++) a[i] = As[cur][ty*8 + i][k];
            const float4 b0 = *(const float4*)&Bs[cur][k][tx*4];
            const float4 b1 = *(const float4*)&Bs[cur][k][64 + tx*4];
            const float bb[8] = {b0.x, b0.y, b0.z, b0.w, b1.x, b1.y, b1.z, b1.w};
#pragma unroll
            for (int i = 0; i < 8; i++)
#pragma unroll
                for (int j = 0; j < 8; j++)
                    acc[i][j] += a[i] * bb[j];
        }

        if (kb + 1 < nk) asm volatile("cp.async.wait_group 0;");
        __syncthreads();
    }
#undef LOADSTAGE

    // epilogue
    const int gr0 = br*128 + ty*8;
    const int n0  = bc*128 + tx*4;
    const int n1  = n0 + 64;
    const float4 bv0 = *(const float4*)&bias[n0];
    const float4 bv1 = *(const float4*)&bias[n1];

    if (MODE == 0){
#pragma unroll
        for (int i = 0; i < 8; i++){
            float4 v0 = make_float4(acc[i][0]+bv0.x, acc[i][1]+bv0.y,
                                    acc[i][2]+bv0.z, acc[i][3]+bv0.w);
            float4 v1 = make_float4(acc[i][4]+bv1.x, acc[i][5]+bv1.y,
                                    acc[i][6]+bv1.z, acc[i][7]+bv1.w);
            *(float4*)&Cout[(size_t)(gr0+i)*N + n0] = v0;
            *(float4*)&Cout[(size_t)(gr0+i)*N + n1] = v1;
        }
    } else {
        // scatter qkv[row, n] -> {Q,K,V}[b, h, t, d]
        const int w0 = n0 / C_; const int r0 = n0 - w0*C_; const int h0 = r0 >> 6; const int d0 = r0 & 63;
        const int w1 = n1 / C_; const int r1 = n1 - w1*C_; const int h1 = r1 >> 6; const int d1 = r1 & 63;
        float* dst0 = (w0 == 0) ? g_Q : ((w0 == 1) ? g_K : g_V);
        float* dst1 = (w1 == 0) ? g_Q : ((w1 == 1) ? g_K : g_V);
#pragma unroll
        for (int i = 0; i < 8; i++){
            const int row = gr0 + i;
            const int b = row >> 10;
            const int t = row & 1023;
            float4 v0 = make_float4(acc[i][0]+bv0.x, acc[i][1]+bv0.y,
                                    acc[i][2]+bv0.z, acc[i][3]+bv0.w);
            float4 v1 = make_float4(acc[i][4]+bv1.x, acc[i][5]+bv1.y,
                                    acc[i][6]+bv1.z, acc[i][7]+bv1.w);
            *(float4*)&dst0[((size_t)(b*H_ + h0)*T_ + t)*HS_ + d0] = v0;
            *(float4*)&dst1[((size_t)(b*H_ + h1)*T_ + t)*HS_ + d1] = v1;
        }
    }
}

// ---------------------------------------------------------------------------
// Flash attention (fp32, causal). One block per (q-tile of 64, bh).
// 256 threads; thread (ty,tx) owns a 4x4 micro-tile: rows ty*4.., cols tx*4..
// smem: Qst[d][r] (pad 68), Kst[d][c] (pad 68), Ps[r][c] (pad 68), Vs[c][d] (64)
// ---------------------------------------------------------------------------
constexpr int SMEM_ATTN = (3*64*68 + 64*64) * 4;   // 68608 bytes

__global__ __launch_bounds__(256)
void attn_kernel()
{
    extern __shared__ float sm[];
    float* Qst = sm;                 // 64*68
    float* Kst = sm + 64*68;         // 64*68
    float* Ps  = sm + 2*64*68;       // 64*68
    float* Vs  = sm + 3*64*68;       // 64*64

    const int qt  = blockIdx.x;      // 0..15
    const int bh  = blockIdx.y;      // 0..95
    const int tid = threadIdx.x;
    const int ty  = tid >> 4;
    const int tx  = tid & 15;

    const float* Qb = g_Q + (size_t)bh * (T_*HS_);
    const float* Kb = g_K + (size_t)bh * (T_*HS_);
    const float* Vb = g_V + (size_t)bh * (T_*HS_);

    // Load Q tile, scaled by 1/sqrt(hs)=0.125, transposed to [d][r]
    for (int idx = tid; idx < 64*16; idx += 256){
        const int r  = idx >> 4;
        const int dq = (idx & 15) << 2;
        const float4 q = *(const float4*)&Qb[(size_t)(qt*64 + r)*HS_ + dq];
        Qst[(dq+0)*68 + r] = q.x * 0.125f;
        Qst[(dq+1)*68 + r] = q.y * 0.125f;
        Qst[(dq+2)*68 + r] = q.z * 0.125f;
        Qst[(dq+3)*68 + r] = q.w * 0.125f;
    }

    float m[4], l[4], o[4][4];
#pragma unroll
    for (int i = 0; i < 4; i++){
        m[i] = -1e30f; l[i] = 0.f;
#pragma unroll
        for (int j = 0; j < 4; j++) o[i][j] = 0.f;
    }

    for (int kt = 0; kt <= qt; kt++){
        __syncthreads();   // prior P@V reads done; (kt=0) also orders Q writes

        // Load K tile transposed [d][c] and V tile natural [c][d]
        for (int idx = tid; idx < 64*16; idx += 256){
            const int r  = idx >> 4;
            const int dq = (idx & 15) << 2;
            const float4 kq = *(const float4*)&Kb[(size_t)(kt*64 + r)*HS_ + dq];
            Kst[(dq+0)*68 + r] = kq.x;
            Kst[(dq+1)*68 + r] = kq.y;
            Kst[(dq+2)*68 + r] = kq.z;
            Kst[(dq+3)*68 + r] = kq.w;
            const float4 vq = *(const float4*)&Vb[(size_t)(kt*64 + r)*HS_ + dq];
            *(float4*)&Vs[r*64 + dq] = vq;
        }
        __syncthreads();

        // S = (Q*scale) @ K^T  (4x4 per thread)
        float s[4][4];
#pragma unroll
        for (int i = 0; i < 4; i++)
#pragma unroll
            for (int j = 0; j < 4; j++) s[i][j] = 0.f;

#pragma unroll 8
        for (int d = 0; d < 64; d++){
            const float4 a = *(const float4*)&Qst[d*68 + ty*4];
            const float4 b = *(const float4*)&Kst[d*68 + tx*4];
            const float av[4] = {a.x, a.y, a.z, a.w};
            const float bv[4] = {b.x, b.y, b.z, b.w};
#pragma unroll
            for (int i = 0; i < 4; i++)
#pragma unroll
                for (int j = 0; j < 4; j++)
                    s[i][j] += av[i] * bv[j];
        }

        // causal mask on diagonal tile
        if (kt == qt){
#pragma unroll
            for (int i = 0; i < 4; i++)
#pragma unroll
                for (int j = 0; j < 4; j++)
                    if (tx*4 + j > ty*4 + i) s[i][j] = -1e30f;
        }

        // online softmax per row (reduce across the 16 tx lanes)
#pragma unroll
        for (int i = 0; i < 4; i++){
            float rm = fmaxf(fmaxf(s[i][0], s[i][1]), fmaxf(s[i][2], s[i][3]));
#pragma unroll
            for (int off = 1; off < 16; off <<= 1)
                rm = fmaxf(rm, __shfl_xor_sync(0xffffffffu, rm, off));
            const float mn = fmaxf(m[i], rm);
            const float alpha = __expf(m[i] - mn);
            m[i] = mn;
            const float p0 = __expf(s[i][0] - mn);
            const float p1 = __expf(s[i][1] - mn);
            const float p2 = __expf(s[i][2] - mn);
            const float p3 = __expf(s[i][3] - mn);
            float rs = p0 + p1 + p2 + p3;
#pragma unroll
            for (int off = 1; off < 16; off <<= 1)
                rs += __shfl_xor_sync(0xffffffffu, rs, off);
            l[i] = l[i]*alpha + rs;
#pragma unroll
            for (int j = 0; j < 4; j++) o[i][j] *= alpha;
            *(float4*)&Ps[(ty*4 + i)*68 + tx*4] = make_float4(p0, p1, p2, p3);
        }
        __syncthreads();

        // O += P @ V
#pragma unroll 8
        for (int c = 0; c < 64; c++){
            const float4 v = *(const float4*)&Vs[c*64 + tx*4];
            const float pa = Ps[(ty*4 + 0)*68 + c];
            const float pb = Ps[(ty*4 + 1)*68 + c];
            const float pc = Ps[(ty*4 + 2)*68 + c];
            const float pd = Ps[(ty*4 + 3)*68 + c];
            o[0][0] += pa*v.x; o[0][1] += pa*v.y; o[0][2] += pa*v.z; o[0][3] += pa*v.w;
            o[1][0] += pb*v.x; o[1][1] += pb*v.y; o[1][2] += pb*v.z; o[1][3] += pb*v.w;
            o[2][0] += pc*v.x; o[2][1] += pc*v.y; o[2][2] += pc*v.z; o[2][3] += pc*v.w;
            o[3][0] += pd*v.x; o[3][1] += pd*v.y; o[3][2] += pd*v.z; o[3][3] += pd*v.w;
        }
    }

    // write Y in [B,T,C] layout
    const int bq = bh / H_;
    const int h  = bh % H_;
#pragma unroll
    for (int i = 0; i < 4; i++){
        const float inv = 1.f / l[i];
        const int t = qt*64 + ty*4 + i;
        float4 out = make_float4(o[i][0]*inv, o[i][1]*inv, o[i][2]*inv, o[i][3]*inv);
        *(float4*)&g_Y[((size_t)(bq*T_ + t))*C_ + h*HS_ + tx*4] = out;
    }
}

// ---------------------------------------------------------------------------
extern "C" void kernel_launch(void* const* d_in, const int* in_sizes, int n_in,
                              void* d_out, int out_size)
{
    const float* x      = (const float*)d_in[0];
    const float* w_attn = (const float*)d_in[1];
    const float* b_attn = (const float*)d_in[2];
    const float* w_proj = (const float*)d_in[3];
    const float* b_proj = (const float*)d_in[4];
    float* out = (float*)d_out;

    // 1) QKV projection + scatter into [B,H,T,hs]
    sgemm_kernel<1><<<dim3((3*C_)/128, M_/128), 256>>>(
        x, w_attn, b_attn, nullptr, M_, 3*C_, C_);

    // 2) causal flash attention -> g_Y [B,T,C]
    cudaFuncSetAttribute(attn_kernel,
                         cudaFuncAttributeMaxDynamicSharedMemorySize, SMEM_ATTN);
    attn_kernel<<<dim3(T_/64, B_*H_), 256, SMEM_ATTN>>>();

    // 3) output projection -> d_out
    sgemm_kernel<0><<<dim3(C_/128, M_/128), 256>>>(
        nullptr, w_proj, b_proj, out, M_, C_, C_);
}

// round 3
// speedup vs baseline: 1.3831x; 1.3831x over previous
#include <cuda_runtime.h>
#include <cuda_bf16.h>
#include <cstdint>

// Problem constants
#define B_  8
#define T_  1024
#define C_  768
#define H_  12
#define HS_ 64
#define M_  8192   // B*T

// ---------------------------------------------------------------------------
// Device-global scratch (no runtime allocation allowed)
// ---------------------------------------------------------------------------
__device__ float g_Q[B_*H_*T_*HS_];
__device__ float g_K[B_*H_*T_*HS_];
__device__ float g_V[B_*H_*T_*HS_];
__device__ float g_Y[(size_t)M_*C_];

__device__ __nv_bfloat16 g_XH[(size_t)M_*C_], g_XL[(size_t)M_*C_];
__device__ __nv_bfloat16 g_YH[(size_t)M_*C_], g_YL[(size_t)M_*C_];
__device__ __nv_bfloat16 g_WaH[(size_t)3*C_*C_], g_WaL[(size_t)3*C_*C_];
__device__ __nv_bfloat16 g_WpH[(size_t)C_*C_],   g_WpL[(size_t)C_*C_];

// ---------------------------------------------------------------------------
// Helpers (portable PTX only — no tcgen05 / no arch-specific features)
// ---------------------------------------------------------------------------
__device__ __forceinline__ uint32_t smem_u32(const void* p){
    return (uint32_t)__cvta_generic_to_shared(p);
}
__device__ __forceinline__ void cpa16(uint32_t d, const void* s){
    asm volatile("cp.async.cg.shared.global [%0], [%1], 16;" :: "r"(d), "l"(s));
}
__device__ __forceinline__ uint32_t lds32(uint32_t a){
    uint32_t v;
    asm volatile("ld.shared.b32 %0, [%1];" : "=r"(v) : "r"(a));
    return v;
}
__device__ __forceinline__ void mma16816(float acc[4], const uint32_t a[4],
                                         const uint32_t b[2]){
    asm volatile(
        "mma.sync.aligned.m16n8k16.row.col.f32.bf16.bf16.f32 "
        "{%0,%1,%2,%3}, {%4,%5,%6,%7}, {%8,%9}, {%0,%1,%2,%3};"
        : "+f"(acc[0]), "+f"(acc[1]), "+f"(acc[2]), "+f"(acc[3])
        : "r"(a[0]), "r"(a[1]), "r"(a[2]), "r"(a[3]), "r"(b[0]), "r"(b[1]));
}

// ---------------------------------------------------------------------------
// Pre-pass: split fp32 -> bf16 hi/lo.  WHICH=0: x (param) -> XH/XL
//                                      WHICH=1: g_Y       -> YH/YL
// ---------------------------------------------------------------------------
template<int WHICH>
__global__ void convert_split(const float* __restrict__ src_param)
{
    const float* src = (WHICH == 0) ? src_param : g_Y;
    __nv_bfloat16* Hh = (WHICH == 0) ? g_XH : g_YH;
    __nv_bfloat16* Ll = (WHICH == 0) ? g_XL : g_YL;

    const int i = blockIdx.x * blockDim.x + threadIdx.x;   // float4 index
    const int n4 = (M_*C_) / 4;
    if (i >= n4) return;
    const float4 v = ((const float4*)src)[i];
    __nv_bfloat16 h0 = __float2bfloat16(v.x);
    __nv_bfloat16 h1 = __float2bfloat16(v.y);
    __nv_bfloat16 h2 = __float2bfloat16(v.z);
    __nv_bfloat16 h3 = __float2bfloat16(v.w);
    __nv_bfloat16 l0 = __float2bfloat16(v.x - __bfloat162float(h0));
    __nv_bfloat16 l1 = __float2bfloat16(v.y - __bfloat162float(h1));
    __nv_bfloat16 l2 = __float2bfloat16(v.z - __bfloat162float(h2));
    __nv_bfloat16 l3 = __float2bfloat16(v.w - __bfloat162float(h3));
    __nv_bfloat162 hp0; hp0.x = h0; hp0.y = h1;
    __nv_bfloat162 hp1; hp1.x = h2; hp1.y = h3;
    __nv_bfloat162 lp0; lp0.x = l0; lp0.y = l1;
    __nv_bfloat162 lp1; lp1.x = l2; lp1.y = l3;
    ((__nv_bfloat162*)Hh)[i*2    ] = hp0;
    ((__nv_bfloat162*)Hh)[i*2 + 1] = hp1;
    ((__nv_bfloat162*)Ll)[i*2    ] = lp0;
    ((__nv_bfloat162*)Ll)[i*2 + 1] = lp1;
}

// ---------------------------------------------------------------------------
// Pre-pass: transpose + split weights. w is [K=768][N] row-major; output
// [N][768] bf16 hi/lo (i.e. K-major / "col-major B" for mma.row.col).
// ---------------------------------------------------------------------------
template<int WHICH>
__global__ void transpose_split(const float* __restrict__ w)
{
    constexpr int N = (WHICH == 0) ? 3*C_ : C_;
    __nv_bfloat16* Hh = (WHICH == 0) ? g_WaH : g_WpH;
    __nv_bfloat16* Ll = (WHICH == 0) ? g_WaL : g_WpL;

    __shared__ float tile[32][33];
    const int nb = blockIdx.x * 32;
    const int kb = blockIdx.y * 32;
    const int tx = threadIdx.x;   // 0..31
    const int ty = threadIdx.y;   // 0..7

    #pragma unroll
    for (int i = ty; i < 32; i += 8)
        tile[i][tx] = w[(size_t)(kb + i) * N + nb + tx];
    __syncthreads();

    #pragma unroll
    for (int i = ty; i < 32; i += 8){
        const float v = tile[tx][i];            // = w[kb+tx][nb+i]
        const __nv_bfloat16 h = __float2bfloat16(v);
        const __nv_bfloat16 l = __float2bfloat16(v - __bfloat162float(h));
        const size_t o = (size_t)(nb + i) * C_ + kb + tx;
        Hh[o] = h;
        Ll[o] = l;
    }
}

// ---------------------------------------------------------------------------
// Tensor-core GEMM via mma.sync (bf16 hi/lo, fp32 accum, 3-pass compensation)
// D[128x128] per CTA = A[128 rows][768] @ B^T where B is [N][768] K-major.
// 8 warps: 2(m) x 4(n), warp tile 64x32. BK=32, 2-stage cp.async pipeline.
// smem rows are 80B apart (32 bf16 + 16B pad) -> (20r+c) mod 32 banks,
// conflict-free for the m16n8k16 fragment pattern.
// MODE 1: A=XH/XL, B=WaH/WaL, scatter epilogue -> g_Q/g_K/g_V
// MODE 0: A=YH/YL, B=WpH/WpL, epilogue -> Cout (d_out)
// ---------------------------------------------------------------------------
constexpr int ROWB   = 80;           // bytes per smem row (32 bf16 + pad)
constexpr int MATB   = 128 * ROWB;   // 10240 B per matrix tile
constexpr int STAGEB = 4 * MATB;     // 40960 B per stage (AH,AL,BH,BL)
constexpr int GEMM_SMEM = 2 * STAGEB;// 81920 B

template<int MODE>
__global__ __launch_bounds__(256, 1)
void mma_gemm(const float* __restrict__ bias, float* __restrict__ Cout)
{
    extern __shared__ __align__(128) uint8_t smem[];

    const __nv_bfloat16* AH = (MODE == 1) ? g_XH : g_YH;
    const __nv_bfloat16* AL = (MODE == 1) ? g_XL : g_YL;
    const __nv_bfloat16* BH = (MODE == 1) ? g_WaH : g_WpH;
    const __nv_bfloat16* BL = (MODE == 1) ? g_WaL : g_WpL;

    const int tid  = threadIdx.x;
    const int lane = tid & 31;
    const int warp = tid >> 5;
    const int wm   = warp & 1;        // 0..1 -> m offset wm*64
    const int wn   = warp >> 1;       // 0..3 -> n offset wn*32
    const int bc   = blockIdx.x;      // N tile
    const int br   = blockIdx.y;      // M tile

    const uint32_t sb = smem_u32(smem);

    auto load_stage = [&](int kt, int s){
        const uint32_t st = sb + (uint32_t)s * STAGEB;
        #pragma unroll
        for (int j = 0; j < 2; j++){
            const int ch  = tid + j*256;       // 0..511
            const int row = ch >> 2;
            const int cc  = ch & 3;
            const uint32_t so = (uint32_t)(row*ROWB + cc*16);
            const size_t ga = (size_t)(br*128 + row) * C_ + kt*32 + cc*8;
            const size_t gb = (size_t)(bc*128 + row) * C_ + kt*32 + cc*8;
            cpa16(st            + so, AH + ga);
            cpa16(st +   MATB   + so, AL + ga);
            cpa16(st + 2*MATB   + so, BH + gb);
            cpa16(st + 3*MATB   + so, BL + gb);
        }
        asm volatile("cp.async.commit_group;");
    };

    float acc[4][4][4];
    #pragma unroll
    for (int i = 0; i < 4; i++)
        #pragma unroll
        for (int j = 0; j < 4; j++)
            #pragma unroll
            for (int q = 0; q < 4; q++) acc[i][j][q] = 0.f;

    constexpr int NK = C_ / 32;    // 24

    load_stage(0, 0);
    asm volatile("cp.async.wait_group 0;");
    __syncthreads();

    const int r  = lane >> 2;
    const int c4 = lane & 3;

    for (int kt = 0; kt < NK; kt++){
        const int cur = kt & 1;
        if (kt + 1 < NK) load_stage(kt + 1, cur ^ 1);

        const uint32_t st = sb + (uint32_t)cur * STAGEB;

        #pragma unroll
        for (int kk = 0; kk < 2; kk++){
            uint32_t ah[4][4], al[4][4], bh[4][2], bl[4][2];
            #pragma unroll
            for (int i = 0; i < 4; i++){
                const uint32_t a0 = st + (uint32_t)((wm*64 + i*16 + r)*ROWB
                                                    + kk*32 + c4*4);
                ah[i][0] = lds32(a0);
                ah[i][1] = lds32(a0 + 8*ROWB);
                ah[i][2] = lds32(a0 + 16);
                ah[i][3] = lds32(a0 + 8*ROWB + 16);
                al[i][0] = lds32(a0 + MATB);
                al[i][1] = lds32(a0 + MATB + 8*ROWB);
                al[i][2] = lds32(a0 + MATB + 16);
                al[i][3] = lds32(a0 + MATB + 8*ROWB + 16);
            }
            #pragma unroll
            for (int j = 0; j < 4; j++){
                const uint32_t b0 = st + 2*MATB
                                  + (uint32_t)((wn*32 + j*8 + r)*ROWB
                                               + kk*32 + c4*4);
                bh[j][0] = lds32(b0);
                bh[j][1] = lds32(b0 + 16);
                bl[j][0] = lds32(b0 + MATB);
                bl[j][1] = lds32(b0 + MATB + 16);
            }
            #pragma unroll
            for (int i = 0; i < 4; i++)
                #pragma unroll
                for (int j = 0; j < 4; j++){
                    mma16816(acc[i][j], ah[i], bh[j]);
                    mma16816(acc[i][j], ah[i], bl[j]);
                    mma16816(acc[i][j], al[i], bh[j]);
                }
        }

        if (kt + 1 < NK) asm volatile("cp.async.wait_group 0;");
        __syncthreads();
    }

    // Epilogue: fragment (row = lane/4 [+8], cols = (lane%4)*2, +1)
    #pragma unroll
    for (int j = 0; j < 4; j++){
        const int col = bc*128 + wn*32 + j*8 + c4*2;
        const float2 bv = *(const float2*)&bias[col];
        #pragma unroll
        for (int i = 0; i < 4; i++){
            const int row0 = br*128 + wm*64 + i*16 + r;
            float2 v0 = make_float2(acc[i][j][0] + bv.x, acc[i][j][1] + bv.y);
            float2 v1 = make_float2(acc[i][j][2] + bv.x, acc[i][j][3] + bv.y);
            if (MODE == 0){
                *(float2*)&Cout[(size_t)row0     * C_ + col] = v0;
                *(float2*)&Cout[(size_t)(row0+8) * C_ + col] = v1;
            } else {
                const int which = col / C_;
                const int rem   = col - which * C_;
                const int h = rem >> 6;
                const int d = rem & 63;
                float* dst = (which == 0) ? g_Q : ((which == 1) ? g_K : g_V);
                const int b0 = row0 >> 10, t0 = row0 & 1023;
                const int b1 = (row0+8) >> 10, t1 = (row0+8) & 1023;
                *(float2*)&dst[((size_t)(b0*H_ + h) * T_ + t0) * HS_ + d] = v0;
                *(float2*)&dst[((size_t)(b1*H_ + h) * T_ + t1) * HS_ + d] = v1;
            }
        }
    }
}

// ---------------------------------------------------------------------------
// Flash attention (fp32, causal) — unchanged from the passing R1 kernel.
// ---------------------------------------------------------------------------
constexpr int SMEM_ATTN = (3*64*68 + 64*64) * 4;   // 68608 bytes

__global__ __launch_bounds__(256)
void attn_kernel()
{
    extern __shared__ float sm[];
    float* Qst = sm;                 // 64*68
    float* Kst = sm + 64*68;         // 64*68
    float* Ps  = sm + 2*64*68;       // 64*68
    float* Vs  = sm + 3*64*68;       // 64*64

    const int qt  = blockIdx.x;
    const int bh  = blockIdx.y;
    const int tid = threadIdx.x;
    const int ty  = tid >> 4;
    const int tx  = tid & 15;

    const float* Qb = g_Q + (size_t)bh * (T_*HS_);
    const float* Kb = g_K + (size_t)bh * (T_*HS_);
    const float* Vb = g_V + (size_t)bh * (T_*HS_);

    for (int idx = tid; idx < 64*16; idx += 256){
        const int r  = idx >> 4;
        const int dq = (idx & 15) << 2;
        const float4 q = *(const float4*)&Qb[(size_t)(qt*64 + r)*HS_ + dq];
        Qst[(dq+0)*68 + r] = q.x * 0.125f;
        Qst[(dq+1)*68 + r] = q.y * 0.125f;
        Qst[(dq+2)*68 + r] = q.z * 0.125f;
        Qst[(dq+3)*68 + r] = q.w * 0.125f;
    }

    float m[4], l[4], o[4][4];
#pragma unroll
    for (int i = 0; i < 4; i++){
        m[i] = -1e30f; l[i] = 0.f;
#pragma unroll
        for (int j = 0; j < 4; j++) o[i][j] = 0.f;
    }

    for (int kt = 0; kt <= qt; kt++){
        __syncthreads();

        for (int idx = tid; idx < 64*16; idx += 256){
            const int r  = idx >> 4;
            const int dq = (idx & 15) << 2;
            const float4 kq = *(const float4*)&Kb[(size_t)(kt*64 + r)*HS_ + dq];
            Kst[(dq+0)*68 + r] = kq.x;
            Kst[(dq+1)*68 + r] = kq.y;
            Kst[(dq+2)*68 + r] = kq.z;
            Kst[(dq+3)*68 + r] = kq.w;
            const float4 vq = *(const float4*)&Vb[(size_t)(kt*64 + r)*HS_ + dq];
            *(float4*)&Vs[r*64 + dq] = vq;
        }
        __syncthreads();

        float s[4][4];
#pragma unroll
        for (int i = 0; i < 4; i++)
#pragma unroll
            for (int j = 0; j < 4; j++) s[i][j] = 0.f;

#pragma unroll 8
        for (int d = 0; d < 64; d++){
            const float4 a = *(const float4*)&Qst[d*68 + ty*4];
            const float4 b = *(const float4*)&Kst[d*68 + tx*4];
            const float av[4] = {a.x, a.y, a.z, a.w};
            const float bv[4] = {b.x, b.y, b.z, b.w};
#pragma unroll
            for (int i = 0; i < 4; i++)
#pragma unroll
                for (int j = 0; j < 4; j++)
                    s[i][j] += av[i] * bv[j];
        }

        if (kt == qt){
#pragma unroll
            for (int i = 0; i < 4; i++)
#pragma unroll
                for (int j = 0; j < 4; j++)
                    if (tx*4 + j > ty*4 + i) s[i][j] = -1e30f;
        }

#pragma unroll
        for (int i = 0; i < 4; i++){
            float rm = fmaxf(fmaxf(s[i][0], s[i][1]), fmaxf(s[i][2], s[i][3]));
#pragma unroll
            for (int off = 1; off < 16; off <<= 1)
                rm = fmaxf(rm, __shfl_xor_sync(0xffffffffu, rm, off));
            const float mn = fmaxf(m[i], rm);
            const float alpha = __expf(m[i] - mn);
            m[i] = mn;
            const float p0 = __expf(s[i][0] - mn);
            const float p1 = __expf(s[i][1] - mn);
            const float p2 = __expf(s[i][2] - mn);
            const float p3 = __expf(s[i][3] - mn);
            float rs = p0 + p1 + p2 + p3;
#pragma unroll
            for (int off = 1; off < 16; off <<= 1)
                rs += __shfl_xor_sync(0xffffffffu, rs, off);
            l[i] = l[i]*alpha + rs;
#pragma unroll
            for (int j = 0; j < 4; j++) o[i][j] *= alpha;
            *(float4*)&Ps[(ty*4 + i)*68 + tx*4] = make_float4(p0, p1, p2, p3);
        }
        __syncthreads();

#pragma unroll 8
        for (int c = 0; c < 64; c++){
            const float4 v = *(const float4*)&Vs[c*64 + tx*4];
            const float pa = Ps[(ty*4 + 0)*68 + c];
            const float pb = Ps[(ty*4 + 1)*68 + c];
            const float pc = Ps[(ty*4 + 2)*68 + c];
            const float pd = Ps[(ty*4 + 3)*68 + c];
            o[0][0] += pa*v.x; o[0][1] += pa*v.y; o[0][2] += pa*v.z; o[0][3] += pa*v.w;
            o[1][0] += pb*v.x; o[1][1] += pb*v.y; o[1][2] += pb*v.z; o[1][3] += pb*v.w;
            o[2][0] += pc*v.x; o[2][1] += pc*v.y; o[2][2] += pc*v.z; o[2][3] += pc*v.w;
            o[3][0] += pd*v.x; o[3][1] += pd*v.y; o[3][2] += pd*v.z; o[3][3] += pd*v.w;
        }
    }

    const int bq = bh / H_;
    const int h  = bh % H_;
#pragma unroll
    for (int i = 0; i < 4; i++){
        const float inv = 1.f / l[i];
        const int t = qt*64 + ty*4 + i;
        float4 out = make_float4(o[i][0]*inv, o[i][1]*inv, o[i][2]*inv, o[i][3]*inv);
        *(float4*)&g_Y[((size_t)(bq*T_ + t))*C_ + h*HS_ + tx*4] = out;
    }
}

// ---------------------------------------------------------------------------
extern "C" void kernel_launch(void* const* d_in, const int* in_sizes, int n_in,
                              void* d_out, int out_size)
{
    const float* x      = (const float*)d_in[0];
    const float* w_attn = (const float*)d_in[1];
    const float* b_attn = (const float*)d_in[2];
    const float* w_proj = (const float*)d_in[3];
    const float* b_proj = (const float*)d_in[4];
    float* out = (float*)d_out;

    cudaFuncSetAttribute(mma_gemm<1>, cudaFuncAttributeMaxDynamicSharedMemorySize, GEMM_SMEM);
    cudaFuncSetAttribute(mma_gemm<0>, cudaFuncAttributeMaxDynamicSharedMemorySize, GEMM_SMEM);
    cudaFuncSetAttribute(attn_kernel, cudaFuncAttributeMaxDynamicSharedMemorySize, SMEM_ATTN);

    // 1) split x -> bf16 hi/lo; transpose+split weights
    convert_split<0><<<(M_*C_/4 + 255)/256, 256>>>(x);
    transpose_split<0><<<dim3(3*C_/32, C_/32), dim3(32, 8)>>>(w_attn);
    transpose_split<1><<<dim3(C_/32,   C_/32), dim3(32, 8)>>>(w_proj);

    // 2) QKV projection on tensor cores (scatter into [B,H,T,hs])
    mma_gemm<1><<<dim3(3*C_/128, M_/128), 256, GEMM_SMEM>>>(b_attn, nullptr);

    // 3) causal flash attention (fp32) -> g_Y
    attn_kernel<<<dim3(T_/64, B_*H_), 256, SMEM_ATTN>>>();

    // 4) split attention output, then output projection on tensor cores
    convert_split<1><<<(M_*C_/4 + 255)/256, 256>>>(nullptr);
    mma_gemm<0><<<dim3(C_/128, M_/128), 256, GEMM_SMEM>>>(b_proj, out);
}

// round 5
// speedup vs baseline: 2.1060x; 1.5227x over previous
#include <cuda_runtime.h>
#include <cuda_bf16.h>
#include <cstdint>

// Problem constants
#define B_  8
#define T_  1024
#define C_  768
#define H_  12
#define HS_ 64
#define M_  8192   // B*T

// ---------------------------------------------------------------------------
// Device-global scratch (no runtime allocation allowed)
// ---------------------------------------------------------------------------
__device__ __nv_bfloat16 g_XH[(size_t)M_*C_], g_XL[(size_t)M_*C_];
__device__ __nv_bfloat16 g_YH[(size_t)M_*C_], g_YL[(size_t)M_*C_];
__device__ __nv_bfloat16 g_WaH[(size_t)3*C_*C_], g_WaL[(size_t)3*C_*C_];
__device__ __nv_bfloat16 g_WpH[(size_t)C_*C_],   g_WpL[(size_t)C_*C_];

// Q/K: [B,H,T,hs] bf16 hi/lo (Q prescaled by 0.125). V: TRANSPOSED [B,H,hs,T].
__device__ __nv_bfloat16 g_Qh[B_*H_*T_*HS_], g_Ql[B_*H_*T_*HS_];
__device__ __nv_bfloat16 g_Kh[B_*H_*T_*HS_], g_Kl[B_*H_*T_*HS_];
__device__ __nv_bfloat16 g_Vh[B_*H_*T_*HS_], g_Vl[B_*H_*T_*HS_];

// ---------------------------------------------------------------------------
// Helpers (portable PTX only — compiles for plain sm_103 target)
// ---------------------------------------------------------------------------
__device__ __forceinline__ uint32_t smem_u32(const void* p){
    return (uint32_t)__cvta_generic_to_shared(p);
}
__device__ __forceinline__ void cpa16(uint32_t d, const void* s){
    asm volatile("cp.async.cg.shared.global [%0], [%1], 16;" :: "r"(d), "l"(s));
}
__device__ __forceinline__ uint32_t lds32(uint32_t a){
    uint32_t v;
    asm volatile("ld.shared.b32 %0, [%1];" : "=r"(v) : "r"(a));
    return v;
}
__device__ __forceinline__ void mma16816(float acc[4], const uint32_t a[4],
                                         const uint32_t b[2]){
    asm volatile(
        "mma.sync.aligned.m16n8k16.row.col.f32.bf16.bf16.f32 "
        "{%0,%1,%2,%3}, {%4,%5,%6,%7}, {%8,%9}, {%0,%1,%2,%3};"
        : "+f"(acc[0]), "+f"(acc[1]), "+f"(acc[2]), "+f"(acc[3])
        : "r"(a[0]), "r"(a[1]), "r"(a[2]), "r"(a[3]), "r"(b[0]), "r"(b[1]));
}
__device__ __forceinline__ uint32_t packbf(float x, float y){
    __nv_bfloat162 t = __float22bfloat162_rn(make_float2(x, y));
    return *(uint32_t*)&t;
}
__device__ __forceinline__ float bfhi(float x){
    return __bfloat162float(__float2bfloat16(x));
}

// ---------------------------------------------------------------------------
// Pre-pass: split x fp32 -> bf16 hi/lo
// ---------------------------------------------------------------------------
__global__ void convert_split_x(const float* __restrict__ src)
{
    const int i = blockIdx.x * blockDim.x + threadIdx.x;   // float4 index
    const int n4 = (M_*C_) / 4;
    if (i >= n4) return;
    const float4 v = ((const float4*)src)[i];
    const float h0 = bfhi(v.x), h1 = bfhi(v.y), h2 = bfhi(v.z), h3 = bfhi(v.w);
    ((uint32_t*)g_XH)[i*2    ] = packbf(v.x, v.y);
    ((uint32_t*)g_XH)[i*2 + 1] = packbf(v.z, v.w);
    ((uint32_t*)g_XL)[i*2    ] = packbf(v.x - h0, v.y - h1);
    ((uint32_t*)g_XL)[i*2 + 1] = packbf(v.z - h2, v.w - h3);
}

// ---------------------------------------------------------------------------
// Pre-pass: transpose + split weights. w is [K=768][N] row-major; output
// [N][768] bf16 hi/lo (K-major "col-major B" for mma.row.col).
// ---------------------------------------------------------------------------
template<int WHICH>
__global__ void transpose_split(const float* __restrict__ w)
{
    constexpr int N = (WHICH == 0) ? 3*C_ : C_;
    __nv_bfloat16* Hh = (WHICH == 0) ? g_WaH : g_WpH;
    __nv_bfloat16* Ll = (WHICH == 0) ? g_WaL : g_WpL;

    __shared__ float tile[32][33];
    const int nb = blockIdx.x * 32;
    const int kb = blockIdx.y * 32;
    const int tx = threadIdx.x;   // 0..31
    const int ty = threadIdx.y;   // 0..7

    #pragma unroll
    for (int i = ty; i < 32; i += 8)
        tile[i][tx] = w[(size_t)(kb + i) * N + nb + tx];
    __syncthreads();

    #pragma unroll
    for (int i = ty; i < 32; i += 8){
        const float v = tile[tx][i];            // = w[kb+tx][nb+i]
        const __nv_bfloat16 h = __float2bfloat16(v);
        const __nv_bfloat16 l = __float2bfloat16(v - __bfloat162float(h));
        const size_t o = (size_t)(nb + i) * C_ + kb + tx;
        Hh[o] = h;
        Ll[o] = l;
    }
}

// ---------------------------------------------------------------------------
// Tensor-core GEMM (bf16 hi/lo, fp32 accum, 3-pass compensation)
// MODE 1: A=XH/XL, B=WaH/WaL -> scatter bf16 hi/lo into Qh/Ql,Kh/Kl,Vh/Vl(T)
// MODE 0: A=YH/YL, B=WpH/WpL -> fp32 Cout (d_out)
// ---------------------------------------------------------------------------
constexpr int ROWB   = 80;           // bytes per smem row (32 bf16 + pad)
constexpr int MATB   = 128 * ROWB;   // 10240 B per matrix tile
constexpr int STAGEB = 4 * MATB;     // 40960 B per stage (AH,AL,BH,BL)
constexpr int GEMM_SMEM = 2 * STAGEB;// 81920 B

template<int MODE>
__global__ __launch_bounds__(256, 1)
void mma_gemm(const float* __restrict__ bias, float* __restrict__ Cout)
{
    extern __shared__ __align__(128) uint8_t smem[];

    const __nv_bfloat16* AH = (MODE == 1) ? g_XH : g_YH;
    const __nv_bfloat16* AL = (MODE == 1) ? g_XL : g_YL;
    const __nv_bfloat16* BH = (MODE == 1) ? g_WaH : g_WpH;
    const __nv_bfloat16* BL = (MODE == 1) ? g_WaL : g_WpL;

    const int tid  = threadIdx.x;
    const int lane = tid & 31;
    const int warp = tid >> 5;
    const int wm   = warp & 1;
    const int wn   = warp >> 1;
    const int bc   = blockIdx.x;
    const int br   = blockIdx.y;

    const uint32_t sb = smem_u32(smem);

    auto load_stage = [&](int kt, int s){
        const uint32_t st = sb + (uint32_t)s * STAGEB;
        #pragma unroll
        for (int j = 0; j < 2; j++){
            const int ch  = tid + j*256;
            const int row = ch >> 2;
            const int cc  = ch & 3;
            const uint32_t so = (uint32_t)(row*ROWB + cc*16);
            const size_t ga = (size_t)(br*128 + row) * C_ + kt*32 + cc*8;
            const size_t gb = (size_t)(bc*128 + row) * C_ + kt*32 + cc*8;
            cpa16(st            + so, AH + ga);
            cpa16(st +   MATB   + so, AL + ga);
            cpa16(st + 2*MATB   + so, BH + gb);
            cpa16(st + 3*MATB   + so, BL + gb);
        }
        asm volatile("cp.async.commit_group;");
    };

    float acc[4][4][4];
    #pragma unroll
    for (int i = 0; i < 4; i++)
        #pragma unroll
        for (int j = 0; j < 4; j++)
            #pragma unroll
            for (int q = 0; q < 4; q++) acc[i][j][q] = 0.f;

    constexpr int NK = C_ / 32;    // 24

    load_stage(0, 0);
    asm volatile("cp.async.wait_group 0;");
    __syncthreads();

    const int r  = lane >> 2;
    const int c4 = lane & 3;

    for (int kt = 0; kt < NK; kt++){
        const int cur = kt & 1;
        if (kt + 1 < NK) load_stage(kt + 1, cur ^ 1);

        const uint32_t st = sb + (uint32_t)cur * STAGEB;

        #pragma unroll
        for (int kk = 0; kk < 2; kk++){
            uint32_t ah[4][4], al[4][4], bh[4][2], bl[4][2];
            #pragma unroll
            for (int i = 0; i < 4; i++){
                const uint32_t a0 = st + (uint32_t)((wm*64 + i*16 + r)*ROWB
                                                    + kk*32 + c4*4);
                ah[i][0] = lds32(a0);
                ah[i][1] = lds32(a0 + 8*ROWB);
                ah[i][2] = lds32(a0 + 16);
                ah[i][3] = lds32(a0 + 8*ROWB + 16);
                al[i][0] = lds32(a0 + MATB);
                al[i][1] = lds32(a0 + MATB + 8*ROWB);
                al[i][2] = lds32(a0 + MATB + 16);
                al[i][3] = lds32(a0 + MATB + 8*ROWB + 16);
            }
            #pragma unroll
            for (int j = 0; j < 4; j++){
                const uint32_t b0 = st + 2*MATB
                                  + (uint32_t)((wn*32 + j*8 + r)*ROWB
                                               + kk*32 + c4*4);
                bh[j][0] = lds32(b0);
                bh[j][1] = lds32(b0 + 16);
                bl[j][0] = lds32(b0 + MATB);
                bl[j][1] = lds32(b0 + MATB + 16);
            }
            #pragma unroll
            for (int i = 0; i < 4; i++)
                #pragma unroll
                for (int j = 0; j < 4; j++){
                    mma16816(acc[i][j], ah[i], bh[j]);
                    mma16816(acc[i][j], ah[i], bl[j]);
                    mma16816(acc[i][j], al[i], bh[j]);
                }
        }

        if (kt + 1 < NK) asm volatile("cp.async.wait_group 0;");
        __syncthreads();
    }

    // Epilogue
    #pragma unroll
    for (int j = 0; j < 4; j++){
        const int col = bc*128 + wn*32 + j*8 + c4*2;
        const float2 bv = *(const float2*)&bias[col];
        if (MODE == 0){
            #pragma unroll
            for (int i = 0; i < 4; i++){
                const int row0 = br*128 + wm*64 + i*16 + r;
                float2 v0 = make_float2(acc[i][j][0] + bv.x, acc[i][j][1] + bv.y);
                float2 v1 = make_float2(acc[i][j][2] + bv.x, acc[i][j][3] + bv.y);
                *(float2*)&Cout[(size_t)row0     * C_ + col] = v0;
                *(float2*)&Cout[(size_t)(row0+8) * C_ + col] = v1;
            }
        } else {
            const int which = col / C_;
            const int rem   = col - which * C_;
            const int hh = rem >> 6;
            const int dd = rem & 63;
            #pragma unroll
            for (int i = 0; i < 4; i++){
                const int row0 = br*128 + wm*64 + i*16 + r;
                const int b0i = row0 >> 10, t0i = row0 & 1023;
                const int row1 = row0 + 8;
                const int b1i = row1 >> 10, t1i = row1 & 1023;
                float v00 = acc[i][j][0] + bv.x, v01 = acc[i][j][1] + bv.y;
                float v10 = acc[i][j][2] + bv.x, v11 = acc[i][j][3] + bv.y;
                if (which == 0){ v00*=0.125f; v01*=0.125f; v10*=0.125f; v11*=0.125f; }
                if (which < 2){
                    __nv_bfloat16* DH = (which == 0) ? g_Qh : g_Kh;
                    __nv_bfloat16* DL = (which == 0) ? g_Ql : g_Kl;
                    const size_t o0 = ((size_t)(b0i*H_ + hh)*T_ + t0i)*HS_ + dd;
                    const size_t o1 = ((size_t)(b1i*H_ + hh)*T_ + t1i)*HS_ + dd;
                    *(uint32_t*)&DH[o0] = packbf(v00, v01);
                    *(uint32_t*)&DL[o0] = packbf(v00 - bfhi(v00), v01 - bfhi(v01));
                    *(uint32_t*)&DH[o1] = packbf(v10, v11);
                    *(uint32_t*)&DL[o1] = packbf(v10 - bfhi(v10), v11 - bfhi(v11));
                } else {
                    // V transposed: [B,H,d,T]
                    const size_t vb0 = ((size_t)(b0i*H_ + hh)*HS_ + dd)*T_;
                    const size_t vb1 = ((size_t)(b1i*H_ + hh)*HS_ + dd)*T_;
                    g_Vh[vb0      + t0i] = __float2bfloat16(v00);
                    g_Vh[vb0 + T_ + t0i] = __float2bfloat16(v01);
                    g_Vh[vb1      + t1i] = __float2bfloat16(v10);
                    g_Vh[vb1 + T_ + t1i] = __float2bfloat16(v11);
                    g_Vl[vb0      + t0i] = __float2bfloat16(v00 - bfhi(v00));
                    g_Vl[vb0 + T_ + t0i] = __float2bfloat16(v01 - bfhi(v01));
                    g_Vl[vb1      + t1i] = __float2bfloat16(v10 - bfhi(v10));
                    g_Vl[vb1 + T_ + t1i] = __float2bfloat16(v11 - bfhi(v11));
                }
            }
        }
    }
}

// ---------------------------------------------------------------------------
// Tensor-core causal flash attention.
// CTA = (q-tile of 128 rows, bh). 8 warps, warp owns 16 q-rows.
// S = Qh@KhT + Qh@KlT + Ql@KhT (3-pass).
// O += Ph@Vh + Ph@Vl + Pl@Vh (3-pass; P split in-register, only PlVl dropped).
// smem: Q hi/lo [128][64] rows 144B; per-stage K hi/lo [128][64] rows 144B,
//       V hi/lo [64][128] rows 272B (V stored d-major). 2-stage pipeline.
// ---------------------------------------------------------------------------
constexpr int AT_ROWK = 144;
constexpr int AT_ROWV = 272;
constexpr int AT_MK   = 128 * AT_ROWK;   // 18432
constexpr int AT_MV   = 64  * AT_ROWV;   // 17408
constexpr int AT_Q    = 2 * AT_MK;       // 36864
constexpr int AT_STAGE= 2*AT_MK + 2*AT_MV;  // 71680
constexpr int ATTN_SMEM = AT_Q + 2*AT_STAGE;// 180224

__global__ __launch_bounds__(256, 1)
void attn_tc()
{
    extern __shared__ __align__(128) uint8_t smx[];
    const uint32_t sb = smem_u32(smx);

    const int qt  = blockIdx.x;    // 0..7
    const int bh  = blockIdx.y;    // 0..95
    const int tid = threadIdx.x;
    const int lane = tid & 31;
    const int w    = tid >> 5;
    const int r    = lane >> 2;
    const int c4   = lane & 3;

    // ---- async loads ----
    const size_t qoff = ((size_t)bh*T_ + qt*128) * HS_;
    #pragma unroll
    for (int j = 0; j < 4; j++){
        const int ch = tid + 256*j;           // 0..1023
        const int row = ch >> 3, c = ch & 7;
        const uint32_t so = sb + (uint32_t)(row*AT_ROWK + c*16);
        const size_t g = qoff + (size_t)row*HS_ + c*8;
        cpa16(so,         g_Qh + g);
        cpa16(so + AT_MK, g_Ql + g);
    }

    auto load_kv = [&](int kt, int s){
        const uint32_t st = sb + AT_Q + (uint32_t)s * AT_STAGE;
        const size_t koff = ((size_t)bh*T_ + kt*128) * HS_;
        #pragma unroll
        for (int j = 0; j < 4; j++){
            const int ch = tid + 256*j;
            const int row = ch >> 3, c = ch & 7;
            const uint32_t so = st + (uint32_t)(row*AT_ROWK + c*16);
            const size_t g = koff + (size_t)row*HS_ + c*8;
            cpa16(so,         g_Kh + g);
            cpa16(so + AT_MK, g_Kl + g);
        }
        const size_t voff = (size_t)bh*HS_*T_ + kt*128;
        #pragma unroll
        for (int j = 0; j < 4; j++){
            const int ch = tid + 256*j;
            const int row = ch >> 4, c = ch & 15;   // row 0..63
            const uint32_t so = st + 2*AT_MK + (uint32_t)(row*AT_ROWV + c*16);
            const size_t g = voff + (size_t)row*T_ + c*8;
            cpa16(so,         g_Vh + g);
            cpa16(so + AT_MV, g_Vl + g);
        }
        asm volatile("cp.async.commit_group;");
    };

    load_kv(0, 0);   // group 0 = Q + stage0

    float m0 = -1e30f, m1 = -1e30f, l0 = 0.f, l1 = 0.f;
    float o[8][4];
    #pragma unroll
    for (int j2 = 0; j2 < 8; j2++)
        #pragma unroll
        for (int q = 0; q < 4; q++) o[j2][q] = 0.f;

    for (int kt = 0; kt <= qt; kt++){
        if (kt < qt){
            load_kv(kt + 1, (kt + 1) & 1);
            asm volatile("cp.async.wait_group 1;");
        } else {
            asm volatile("cp.async.wait_group 0;");
        }
        __syncthreads();

        const uint32_t st = sb + AT_Q + (uint32_t)(kt & 1) * AT_STAGE;

        // ---- S = Q @ K^T (3-pass hi/lo) ----
        float s[16][4];
        #pragma unroll
        for (int j = 0; j < 16; j++){
            s[j][0] = s[j][1] = s[j][2] = s[j][3] = 0.f;
        }
        #pragma unroll
        for (int kk = 0; kk < 4; kk++){
            const uint32_t qb = sb + (uint32_t)((w*16 + r)*AT_ROWK + kk*32 + c4*4);
            uint32_t qh[4], ql[4];
            qh[0] = lds32(qb);
            qh[1] = lds32(qb + 8*AT_ROWK);
            qh[2] = lds32(qb + 16);
            qh[3] = lds32(qb + 8*AT_ROWK + 16);
            ql[0] = lds32(qb + AT_MK);
            ql[1] = lds32(qb + AT_MK + 8*AT_ROWK);
            ql[2] = lds32(qb + AT_MK + 16);
            ql[3] = lds32(qb + AT_MK + 8*AT_ROWK + 16);
            #pragma unroll
            for (int j = 0; j < 16; j++){
                const uint32_t kb = st + (uint32_t)((j*8 + r)*AT_ROWK + kk*32 + c4*4);
                uint32_t bh2[2], bl2[2];
                bh2[0] = lds32(kb);
                bh2[1] = lds32(kb + 16);
                bl2[0] = lds32(kb + AT_MK);
                bl2[1] = lds32(kb + AT_MK + 16);
                mma16816(s[j], qh, bh2);
                mma16816(s[j], qh, bl2);
                mma16816(s[j], ql, bh2);
            }
        }

        // ---- causal mask on diagonal tile ----
        if (kt == qt){
            const int row0 = w*16 + r;
            #pragma unroll
            for (int j = 0; j < 16; j++){
                const int col0 = j*8 + c4*2;
                if (col0     > row0    ) s[j][0] = -1e30f;
                if (col0 + 1 > row0    ) s[j][1] = -1e30f;
                if (col0     > row0 + 8) s[j][2] = -1e30f;
                if (col0 + 1 > row0 + 8) s[j][3] = -1e30f;
            }
        }

        // ---- online softmax ----
        float rm0 = -1e30f, rm1 = -1e30f;
        #pragma unroll
        for (int j = 0; j < 16; j++){
            rm0 = fmaxf(rm0, fmaxf(s[j][0], s[j][1]));
            rm1 = fmaxf(rm1, fmaxf(s[j][2], s[j][3]));
        }
        rm0 = fmaxf(rm0, __shfl_xor_sync(0xffffffffu, rm0, 1));
        rm0 = fmaxf(rm0, __shfl_xor_sync(0xffffffffu, rm0, 2));
        rm1 = fmaxf(rm1, __shfl_xor_sync(0xffffffffu, rm1, 1));
        rm1 = fmaxf(rm1, __shfl_xor_sync(0xffffffffu, rm1, 2));
        const float mn0 = fmaxf(m0, rm0), mn1 = fmaxf(m1, rm1);
        const float a0 = __expf(m0 - mn0), a1 = __expf(m1 - mn1);
        m0 = mn0; m1 = mn1;
        float rs0 = 0.f, rs1 = 0.f;
        #pragma unroll
        for (int j = 0; j < 16; j++){
            s[j][0] = __expf(s[j][0] - mn0);
            s[j][1] = __expf(s[j][1] - mn0);
            s[j][2] = __expf(s[j][2] - mn1);
            s[j][3] = __expf(s[j][3] - mn1);
            rs0 += s[j][0] + s[j][1];
            rs1 += s[j][2] + s[j][3];
        }
        rs0 += __shfl_xor_sync(0xffffffffu, rs0, 1);
        rs0 += __shfl_xor_sync(0xffffffffu, rs0, 2);
        rs1 += __shfl_xor_sync(0xffffffffu, rs1, 1);
        rs1 += __shfl_xor_sync(0xffffffffu, rs1, 2);
        l0 = l0*a0 + rs0;
        l1 = l1*a1 + rs1;
        #pragma unroll
        for (int j2 = 0; j2 < 8; j2++){
            o[j2][0] *= a0; o[j2][1] *= a0;
            o[j2][2] *= a1; o[j2][3] *= a1;
        }

        // ---- O += P @ V (3-pass: Ph*Vh + Ph*Vl + Pl*Vh) ----
        const uint32_t vbase = st + 2*AT_MK;
        #pragma unroll
        for (int kk = 0; kk < 8; kk++){
            // split P in-register: p = ph + pl (only PlVl term dropped)
            float ph[8], pl[8];
            #pragma unroll
            for (int e = 0; e < 4; e++){
                ph[e]   = bfhi(s[2*kk  ][e]);  pl[e]   = s[2*kk  ][e] - ph[e];
                ph[4+e] = bfhi(s[2*kk+1][e]);  pl[4+e] = s[2*kk+1][e] - ph[4+e];
            }
            uint32_t a_h[4], a_l[4];
            a_h[0] = packbf(ph[0], ph[1]);  a_h[1] = packbf(ph[2], ph[3]);
            a_h[2] = packbf(ph[4], ph[5]);  a_h[3] = packbf(ph[6], ph[7]);
            a_l[0] = packbf(pl[0], pl[1]);  a_l[1] = packbf(pl[2], pl[3]);
            a_l[2] = packbf(pl[4], pl[5]);  a_l[3] = packbf(pl[6], pl[7]);
            #pragma unroll
            for (int j2 = 0; j2 < 8; j2++){
                const uint32_t vb = vbase + (uint32_t)((j2*8 + r)*AT_ROWV
                                                       + kk*32 + c4*4);
                uint32_t vh2[2], vl2[2];
                vh2[0] = lds32(vb);
                vh2[1] = lds32(vb + 16);
                vl2[0] = lds32(vb + AT_MV);
                vl2[1] = lds32(vb + AT_MV + 16);
                mma16816(o[j2], a_h, vh2);
                mma16816(o[j2], a_h, vl2);
                mma16816(o[j2], a_l, vh2);
            }
        }
        __syncthreads();
    }

    // ---- epilogue: write YH/YL bf16 hi/lo [M][768] ----
    const float inv0 = 1.f / l0, inv1 = 1.f / l1;
    const int bq = bh / H_, hh = bh % H_;
    const int t0 = qt*128 + w*16 + r;
    #pragma unroll
    for (int j2 = 0; j2 < 8; j2++){
        const int cc = hh*64 + j2*8 + c4*2;
        const float y0 = o[j2][0]*inv0, y1 = o[j2][1]*inv0;
        const float y2 = o[j2][2]*inv1, y3 = o[j2][3]*inv1;
        const size_t r0 = (size_t)(bq*T_ + t0    )*C_ + cc;
        const size_t r1 = (size_t)(bq*T_ + t0 + 8)*C_ + cc;
        *(uint32_t*)&g_YH[r0] = packbf(y0, y1);
        *(uint32_t*)&g_YL[r0] = packbf(y0 - bfhi(y0), y1 - bfhi(y1));
        *(uint32_t*)&g_YH[r1] = packbf(y2, y3);
        *(uint32_t*)&g_YL[r1] = packbf(y2 - bfhi(y2), y3 - bfhi(y3));
    }
}

// ---------------------------------------------------------------------------
extern "C" void kernel_launch(void* const* d_in, const int* in_sizes, int n_in,
                              void* d_out, int out_size)
{
    const float* x      = (const float*)d_in[0];
    const float* w_attn = (const float*)d_in[1];
    const float* b_attn = (const float*)d_in[2];
    const float* w_proj = (const float*)d_in[3];
    const float* b_proj = (const float*)d_in[4];
    float* out = (float*)d_out;

    cudaFuncSetAttribute(mma_gemm<1>, cudaFuncAttributeMaxDynamicSharedMemorySize, GEMM_SMEM);
    cudaFuncSetAttribute(mma_gemm<0>, cudaFuncAttributeMaxDynamicSharedMemorySize, GEMM_SMEM);
    cudaFuncSetAttribute(attn_tc, cudaFuncAttributeMaxDynamicSharedMemorySize, ATTN_SMEM);

    // 1) split x; transpose+split weights
    convert_split_x<<<(M_*C_/4 + 255)/256, 256>>>(x);
    transpose_split<0><<<dim3(3*C_/32, C_/32), dim3(32, 8)>>>(w_attn);
    transpose_split<1><<<dim3(C_/32,   C_/32), dim3(32, 8)>>>(w_proj);

    // 2) QKV projection -> bf16 hi/lo Q(scaled)/K/V(transposed)
    mma_gemm<1><<<dim3(3*C_/128, M_/128), 256, GEMM_SMEM>>>(b_attn, nullptr);

    // 3) tensor-core causal flash attention -> YH/YL
    attn_tc<<<dim3(T_/128, B_*H_), 256, ATTN_SMEM>>>();

    // 4) output projection -> d_out
    mma_gemm<0><<<dim3(C_/128, M_/128), 256, GEMM_SMEM>>>(b_proj, out);
}

// round 6
// speedup vs baseline: 2.2566x; 1.0715x over previous
#include <cuda_runtime.h>
#include <cuda_bf16.h>
#include <cstdint>

// Problem constants
#define B_  8
#define T_  1024
#define C_  768
#define H_  12
#define HS_ 64
#define M_  8192   // B*T

// ---------------------------------------------------------------------------
// Device-global scratch (no runtime allocation allowed)
// ---------------------------------------------------------------------------
__device__ __nv_bfloat16 g_XH[(size_t)M_*C_], g_XL[(size_t)M_*C_];
__device__ __nv_bfloat16 g_YH[(size_t)M_*C_], g_YL[(size_t)M_*C_];
__device__ __nv_bfloat16 g_WaH[(size_t)3*C_*C_], g_WaL[(size_t)3*C_*C_];
__device__ __nv_bfloat16 g_WpH[(size_t)C_*C_],   g_WpL[(size_t)C_*C_];

// Q/K: [B,H,T,hs] bf16 hi/lo (Q prescaled by 0.125). V: TRANSPOSED [B,H,hs,T].
__device__ __nv_bfloat16 g_Qh[B_*H_*T_*HS_], g_Ql[B_*H_*T_*HS_];
__device__ __nv_bfloat16 g_Kh[B_*H_*T_*HS_], g_Kl[B_*H_*T_*HS_];
__device__ __nv_bfloat16 g_Vh[B_*H_*T_*HS_], g_Vl[B_*H_*T_*HS_];

// ---------------------------------------------------------------------------
// Helpers (portable PTX only — compiles for plain sm_103 target)
// ---------------------------------------------------------------------------
__device__ __forceinline__ uint32_t smem_u32(const void* p){
    return (uint32_t)__cvta_generic_to_shared(p);
}
__device__ __forceinline__ void cpa16(uint32_t d, const void* s){
    asm volatile("cp.async.cg.shared.global [%0], [%1], 16;" :: "r"(d), "l"(s));
}
__device__ __forceinline__ uint32_t lds32(uint32_t a){
    uint32_t v;
    asm volatile("ld.shared.b32 %0, [%1];" : "=r"(v) : "r"(a));
    return v;
}
__device__ __forceinline__ void mma16816(float acc[4], const uint32_t a[4],
                                         const uint32_t b[2]){
    asm volatile(
        "mma.sync.aligned.m16n8k16.row.col.f32.bf16.bf16.f32 "
        "{%0,%1,%2,%3}, {%4,%5,%6,%7}, {%8,%9}, {%0,%1,%2,%3};"
        : "+f"(acc[0]), "+f"(acc[1]), "+f"(acc[2]), "+f"(acc[3])
        : "r"(a[0]), "r"(a[1]), "r"(a[2]), "r"(a[3]), "r"(b[0]), "r"(b[1]));
}
__device__ __forceinline__ uint32_t packbf(float x, float y){
    __nv_bfloat162 t = __float22bfloat162_rn(make_float2(x, y));
    return *(uint32_t*)&t;
}
__device__ __forceinline__ float bfhi(float x){
    return __bfloat162float(__float2bfloat16(x));
}

// ---------------------------------------------------------------------------
// Pre-pass: split x fp32 -> bf16 hi/lo
// ---------------------------------------------------------------------------
__global__ void convert_split_x(const float* __restrict__ src)
{
    const int i = blockIdx.x * blockDim.x + threadIdx.x;   // float4 index
    const int n4 = (M_*C_) / 4;
    if (i >= n4) return;
    const float4 v = ((const float4*)src)[i];
    const float h0 = bfhi(v.x), h1 = bfhi(v.y), h2 = bfhi(v.z), h3 = bfhi(v.w);
    ((uint32_t*)g_XH)[i*2    ] = packbf(v.x, v.y);
    ((uint32_t*)g_XH)[i*2 + 1] = packbf(v.z, v.w);
    ((uint32_t*)g_XL)[i*2    ] = packbf(v.x - h0, v.y - h1);
    ((uint32_t*)g_XL)[i*2 + 1] = packbf(v.z - h2, v.w - h3);
}

// ---------------------------------------------------------------------------
// Pre-pass: transpose + split weights. w is [K=768][N] row-major; output
// [N][768] bf16 hi/lo (K-major "col-major B" for mma.row.col).
// ---------------------------------------------------------------------------
template<int WHICH>
__global__ void transpose_split(const float* __restrict__ w)
{
    constexpr int N = (WHICH == 0) ? 3*C_ : C_;
    __nv_bfloat16* Hh = (WHICH == 0) ? g_WaH : g_WpH;
    __nv_bfloat16* Ll = (WHICH == 0) ? g_WaL : g_WpL;

    __shared__ float tile[32][33];
    const int nb = blockIdx.x * 32;
    const int kb = blockIdx.y * 32;
    const int tx = threadIdx.x;   // 0..31
    const int ty = threadIdx.y;   // 0..7

    #pragma unroll
    for (int i = ty; i < 32; i += 8)
        tile[i][tx] = w[(size_t)(kb + i) * N + nb + tx];
    __syncthreads();

    #pragma unroll
    for (int i = ty; i < 32; i += 8){
        const float v = tile[tx][i];            // = w[kb+tx][nb+i]
        const __nv_bfloat16 h = __float2bfloat16(v);
        const __nv_bfloat16 l = __float2bfloat16(v - __bfloat162float(h));
        const size_t o = (size_t)(nb + i) * C_ + kb + tx;
        Hh[o] = h;
        Ll[o] = l;
    }
}

// ---------------------------------------------------------------------------
// Tensor-core GEMM (bf16 hi/lo, fp32 accum, 3-pass compensation)
// Register-lean inner loop (B fragments resident per kk; A streamed per row)
// + launch_bounds(256,2) => 2 CTAs/SM (16 warps) to cover HMMA latency.
// MODE 1: A=XH/XL, B=WaH/WaL -> scatter bf16 hi/lo into Qh/Ql,Kh/Kl,Vh/Vl(T)
// MODE 0: A=YH/YL, B=WpH/WpL -> fp32 Cout (d_out)
// ---------------------------------------------------------------------------
constexpr int ROWB   = 80;           // bytes per smem row (32 bf16 + pad)
constexpr int MATB   = 128 * ROWB;   // 10240 B per matrix tile
constexpr int STAGEB = 4 * MATB;     // 40960 B per stage (AH,AL,BH,BL)
constexpr int GEMM_SMEM = 2 * STAGEB;// 81920 B

template<int MODE>
__global__ __launch_bounds__(256, 2)
void mma_gemm(const float* __restrict__ bias, float* __restrict__ Cout)
{
    extern __shared__ __align__(128) uint8_t smem[];

    const __nv_bfloat16* AH = (MODE == 1) ? g_XH : g_YH;
    const __nv_bfloat16* AL = (MODE == 1) ? g_XL : g_YL;
    const __nv_bfloat16* BH = (MODE == 1) ? g_WaH : g_WpH;
    const __nv_bfloat16* BL = (MODE == 1) ? g_WaL : g_WpL;

    const int tid  = threadIdx.x;
    const int lane = tid & 31;
    const int warp = tid >> 5;
    const int wm   = warp & 1;
    const int wn   = warp >> 1;
    const int bc   = blockIdx.x;
    const int br   = blockIdx.y;

    const uint32_t sb = smem_u32(smem);

    auto load_stage = [&](int kt, int s){
        const uint32_t st = sb + (uint32_t)s * STAGEB;
        #pragma unroll
        for (int j = 0; j < 2; j++){
            const int ch  = tid + j*256;
            const int row = ch >> 2;
            const int cc  = ch & 3;
            const uint32_t so = (uint32_t)(row*ROWB + cc*16);
            const size_t ga = (size_t)(br*128 + row) * C_ + kt*32 + cc*8;
            const size_t gb = (size_t)(bc*128 + row) * C_ + kt*32 + cc*8;
            cpa16(st            + so, AH + ga);
            cpa16(st +   MATB   + so, AL + ga);
            cpa16(st + 2*MATB   + so, BH + gb);
            cpa16(st + 3*MATB   + so, BL + gb);
        }
        asm volatile("cp.async.commit_group;");
    };

    float acc[4][4][4];
    #pragma unroll
    for (int i = 0; i < 4; i++)
        #pragma unroll
        for (int j = 0; j < 4; j++)
            #pragma unroll
            for (int q = 0; q < 4; q++) acc[i][j][q] = 0.f;

    constexpr int NK = C_ / 32;    // 24

    load_stage(0, 0);
    asm volatile("cp.async.wait_group 0;");
    __syncthreads();

    const int r  = lane >> 2;
    const int c4 = lane & 3;

    for (int kt = 0; kt < NK; kt++){
        const int cur = kt & 1;
        if (kt + 1 < NK) load_stage(kt + 1, cur ^ 1);

        const uint32_t st = sb + (uint32_t)cur * STAGEB;

        #pragma unroll
        for (int kk = 0; kk < 2; kk++){
            // B fragments resident for this kk (16 regs)
            uint32_t bh[4][2], bl[4][2];
            #pragma unroll
            for (int j = 0; j < 4; j++){
                const uint32_t b0 = st + 2*MATB
                                  + (uint32_t)((wn*32 + j*8 + r)*ROWB
                                               + kk*32 + c4*4);
                bh[j][0] = lds32(b0);
                bh[j][1] = lds32(b0 + 16);
                bl[j][0] = lds32(b0 + MATB);
                bl[j][1] = lds32(b0 + MATB + 16);
            }
            // stream A rows: only 8 A regs live at a time
            #pragma unroll
            for (int i = 0; i < 4; i++){
                const uint32_t a0 = st + (uint32_t)((wm*64 + i*16 + r)*ROWB
                                                    + kk*32 + c4*4);
                uint32_t ah[4], al[4];
                ah[0] = lds32(a0);
                ah[1] = lds32(a0 + 8*ROWB);
                ah[2] = lds32(a0 + 16);
                ah[3] = lds32(a0 + 8*ROWB + 16);
                al[0] = lds32(a0 + MATB);
                al[1] = lds32(a0 + MATB + 8*ROWB);
                al[2] = lds32(a0 + MATB + 16);
                al[3] = lds32(a0 + MATB + 8*ROWB + 16);
                #pragma unroll
                for (int j = 0; j < 4; j++){
                    mma16816(acc[i][j], ah, bh[j]);
                    mma16816(acc[i][j], ah, bl[j]);
                    mma16816(acc[i][j], al, bh[j]);
                }
            }
        }

        if (kt + 1 < NK) asm volatile("cp.async.wait_group 0;");
        __syncthreads();
    }

    // Epilogue
    #pragma unroll
    for (int j = 0; j < 4; j++){
        const int col = bc*128 + wn*32 + j*8 + c4*2;
        const float2 bv = *(const float2*)&bias[col];
        if (MODE == 0){
            #pragma unroll
            for (int i = 0; i < 4; i++){
                const int row0 = br*128 + wm*64 + i*16 + r;
                float2 v0 = make_float2(acc[i][j][0] + bv.x, acc[i][j][1] + bv.y);
                float2 v1 = make_float2(acc[i][j][2] + bv.x, acc[i][j][3] + bv.y);
                *(float2*)&Cout[(size_t)row0     * C_ + col] = v0;
                *(float2*)&Cout[(size_t)(row0+8) * C_ + col] = v1;
            }
        } else {
            const int which = col / C_;
            const int rem   = col - which * C_;
            const int hh = rem >> 6;
            const int dd = rem & 63;
            #pragma unroll
            for (int i = 0; i < 4; i++){
                const int row0 = br*128 + wm*64 + i*16 + r;
                const int b0i = row0 >> 10, t0i = row0 & 1023;
                const int row1 = row0 + 8;
                const int b1i = row1 >> 10, t1i = row1 & 1023;
                float v00 = acc[i][j][0] + bv.x, v01 = acc[i][j][1] + bv.y;
                float v10 = acc[i][j][2] + bv.x, v11 = acc[i][j][3] + bv.y;
                if (which == 0){ v00*=0.125f; v01*=0.125f; v10*=0.125f; v11*=0.125f; }
                if (which < 2){
                    __nv_bfloat16* DH = (which == 0) ? g_Qh : g_Kh;
                    __nv_bfloat16* DL = (which == 0) ? g_Ql : g_Kl;
                    const size_t o0 = ((size_t)(b0i*H_ + hh)*T_ + t0i)*HS_ + dd;
                    const size_t o1 = ((size_t)(b1i*H_ + hh)*T_ + t1i)*HS_ + dd;
                    *(uint32_t*)&DH[o0] = packbf(v00, v01);
                    *(uint32_t*)&DL[o0] = packbf(v00 - bfhi(v00), v01 - bfhi(v01));
                    *(uint32_t*)&DH[o1] = packbf(v10, v11);
                    *(uint32_t*)&DL[o1] = packbf(v10 - bfhi(v10), v11 - bfhi(v11));
                } else {
                    // V transposed: [B,H,d,T]
                    const size_t vb0 = ((size_t)(b0i*H_ + hh)*HS_ + dd)*T_;
                    const size_t vb1 = ((size_t)(b1i*H_ + hh)*HS_ + dd)*T_;
                    g_Vh[vb0      + t0i] = __float2bfloat16(v00);
                    g_Vh[vb0 + T_ + t0i] = __float2bfloat16(v01);
                    g_Vh[vb1      + t1i] = __float2bfloat16(v10);
                    g_Vh[vb1 + T_ + t1i] = __float2bfloat16(v11);
                    g_Vl[vb0      + t0i] = __float2bfloat16(v00 - bfhi(v00));
                    g_Vl[vb0 + T_ + t0i] = __float2bfloat16(v01 - bfhi(v01));
                    g_Vl[vb1      + t1i] = __float2bfloat16(v10 - bfhi(v10));
                    g_Vl[vb1 + T_ + t1i] = __float2bfloat16(v11 - bfhi(v11));
                }
            }
        }
    }
}

// ---------------------------------------------------------------------------
// Tensor-core causal flash attention (unchanged from passing R5 kernel).
// ---------------------------------------------------------------------------
constexpr int AT_ROWK = 144;
constexpr int AT_ROWV = 272;
constexpr int AT_MK   = 128 * AT_ROWK;   // 18432
constexpr int AT_MV   = 64  * AT_ROWV;   // 17408
constexpr int AT_Q    = 2 * AT_MK;       // 36864
constexpr int AT_STAGE= 2*AT_MK + 2*AT_MV;  // 71680
constexpr int ATTN_SMEM = AT_Q + 2*AT_STAGE;// 180224

__global__ __launch_bounds__(256, 1)
void attn_tc()
{
    extern __shared__ __align__(128) uint8_t smx[];
    const uint32_t sb = smem_u32(smx);

    const int qt  = blockIdx.x;    // 0..7
    const int bh  = blockIdx.y;    // 0..95
    const int tid = threadIdx.x;
    const int lane = tid & 31;
    const int w    = tid >> 5;
    const int r    = lane >> 2;
    const int c4   = lane & 3;

    // ---- async loads ----
    const size_t qoff = ((size_t)bh*T_ + qt*128) * HS_;
    #pragma unroll
    for (int j = 0; j < 4; j++){
        const int ch = tid + 256*j;           // 0..1023
        const int row = ch >> 3, c = ch & 7;
        const uint32_t so = sb + (uint32_t)(row*AT_ROWK + c*16);
        const size_t g = qoff + (size_t)row*HS_ + c*8;
        cpa16(so,         g_Qh + g);
        cpa16(so + AT_MK, g_Ql + g);
    }

    auto load_kv = [&](int kt, int s){
        const uint32_t st = sb + AT_Q + (uint32_t)s * AT_STAGE;
        const size_t koff = ((size_t)bh*T_ + kt*128) * HS_;
        #pragma unroll
        for (int j = 0; j < 4; j++){
            const int ch = tid + 256*j;
            const int row = ch >> 3, c = ch & 7;
            const uint32_t so = st + (uint32_t)(row*AT_ROWK + c*16);
            const size_t g = koff + (size_t)row*HS_ + c*8;
            cpa16(so,         g_Kh + g);
            cpa16(so + AT_MK, g_Kl + g);
        }
        const size_t voff = (size_t)bh*HS_*T_ + kt*128;
        #pragma unroll
        for (int j = 0; j < 4; j++){
            const int ch = tid + 256*j;
            const int row = ch >> 4, c = ch & 15;   // row 0..63
            const uint32_t so = st + 2*AT_MK + (uint32_t)(row*AT_ROWV + c*16);
            const size_t g = voff + (size_t)row*T_ + c*8;
            cpa16(so,         g_Vh + g);
            cpa16(so + AT_MV, g_Vl + g);
        }
        asm volatile("cp.async.commit_group;");
    };

    load_kv(0, 0);   // group 0 = Q + stage0

    float m0 = -1e30f, m1 = -1e30f, l0 = 0.f, l1 = 0.f;
    float o[8][4];
    #pragma unroll
    for (int j2 = 0; j2 < 8; j2++)
        #pragma unroll
        for (int q = 0; q < 4; q++) o[j2][q] = 0.f;

    for (int kt = 0; kt <= qt; kt++){
        if (kt < qt){
            load_kv(kt + 1, (kt + 1) & 1);
            asm volatile("cp.async.wait_group 1;");
        } else {
            asm volatile("cp.async.wait_group 0;");
        }
        __syncthreads();

        const uint32_t st = sb + AT_Q + (uint32_t)(kt & 1) * AT_STAGE;

        // ---- S = Q @ K^T (3-pass hi/lo) ----
        float s[16][4];
        #pragma unroll
        for (int j = 0; j < 16; j++){
            s[j][0] = s[j][1] = s[j][2] = s[j][3] = 0.f;
        }
        #pragma unroll
        for (int kk = 0; kk < 4; kk++){
            const uint32_t qb = sb + (uint32_t)((w*16 + r)*AT_ROWK + kk*32 + c4*4);
            uint32_t qh[4], ql[4];
            qh[0] = lds32(qb);
            qh[1] = lds32(qb + 8*AT_ROWK);
            qh[2] = lds32(qb + 16);
            qh[3] = lds32(qb + 8*AT_ROWK + 16);
            ql[0] = lds32(qb + AT_MK);
            ql[1] = lds32(qb + AT_MK + 8*AT_ROWK);
            ql[2] = lds32(qb + AT_MK + 16);
            ql[3] = lds32(qb + AT_MK + 8*AT_ROWK + 16);
            #pragma unroll
            for (int j = 0; j < 16; j++){
                const uint32_t kb = st + (uint32_t)((j*8 + r)*AT_ROWK + kk*32 + c4*4);
                uint32_t bh2[2], bl2[2];
                bh2[0] = lds32(kb);
                bh2[1] = lds32(kb + 16);
                bl2[0] = lds32(kb + AT_MK);
                bl2[1] = lds32(kb + AT_MK + 16);
                mma16816(s[j], qh, bh2);
                mma16816(s[j], qh, bl2);
                mma16816(s[j], ql, bh2);
            }
        }

        // ---- causal mask on diagonal tile ----
        if (kt == qt){
            const int row0 = w*16 + r;
            #pragma unroll
            for (int j = 0; j < 16; j++){
                const int col0 = j*8 + c4*2;
                if (col0     > row0    ) s[j][0] = -1e30f;
                if (col0 + 1 > row0    ) s[j][1] = -1e30f;
                if (col0     > row0 + 8) s[j][2] = -1e30f;
                if (col0 + 1 > row0 + 8) s[j][3] = -1e30f;
            }
        }

        // ---- online softmax ----
        float rm0 = -1e30f, rm1 = -1e30f;
        #pragma unroll
        for (int j = 0; j < 16; j++){
            rm0 = fmaxf(rm0, fmaxf(s[j][0], s[j][1]));
            rm1 = fmaxf(rm1, fmaxf(s[j][2], s[j][3]));
        }
        rm0 = fmaxf(rm0, __shfl_xor_sync(0xffffffffu, rm0, 1));
        rm0 = fmaxf(rm0, __shfl_xor_sync(0xffffffffu, rm0, 2));
        rm1 = fmaxf(rm1, __shfl_xor_sync(0xffffffffu, rm1, 1));
        rm1 = fmaxf(rm1, __shfl_xor_sync(0xffffffffu, rm1, 2));
        const float mn0 = fmaxf(m0, rm0), mn1 = fmaxf(m1, rm1);
        const float a0 = __expf(m0 - mn0), a1 = __expf(m1 - mn1);
        m0 = mn0; m1 = mn1;
        float rs0 = 0.f, rs1 = 0.f;
        #pragma unroll
        for (int j = 0; j < 16; j++){
            s[j][0] = __expf(s[j][0] - mn0);
            s[j][1] = __expf(s[j][1] - mn0);
            s[j][2] = __expf(s[j][2] - mn1);
            s[j][3] = __expf(s[j][3] - mn1);
            rs0 += s[j][0] + s[j][1];
            rs1 += s[j][2] + s[j][3];
        }
        rs0 += __shfl_xor_sync(0xffffffffu, rs0, 1);
        rs0 += __shfl_xor_sync(0xffffffffu, rs0, 2);
        rs1 += __shfl_xor_sync(0xffffffffu, rs1, 1);
        rs1 += __shfl_xor_sync(0xffffffffu, rs1, 2);
        l0 = l0*a0 + rs0;
        l1 = l1*a1 + rs1;
        #pragma unroll
        for (int j2 = 0; j2 < 8; j2++){
            o[j2][0] *= a0; o[j2][1] *= a0;
            o[j2][2] *= a1; o[j2][3] *= a1;
        }

        // ---- O += P @ V (3-pass: Ph*Vh + Ph*Vl + Pl*Vh) ----
        const uint32_t vbase = st + 2*AT_MK;
        #pragma unroll
        for (int kk = 0; kk < 8; kk++){
            float ph[8], pl[8];
            #pragma unroll
            for (int e = 0; e < 4; e++){
                ph[e]   = bfhi(s[2*kk  ][e]);  pl[e]   = s[2*kk  ][e] - ph[e];
                ph[4+e] = bfhi(s[2*kk+1][e]);  pl[4+e] = s[2*kk+1][e] - ph[4+e];
            }
            uint32_t a_h[4], a_l[4];
            a_h[0] = packbf(ph[0], ph[1]);  a_h[1] = packbf(ph[2], ph[3]);
            a_h[2] = packbf(ph[4], ph[5]);  a_h[3] = packbf(ph[6], ph[7]);
            a_l[0] = packbf(pl[0], pl[1]);  a_l[1] = packbf(pl[2], pl[3]);
            a_l[2] = packbf(pl[4], pl[5]);  a_l[3] = packbf(pl[6], pl[7]);
            #pragma unroll
            for (int j2 = 0; j2 < 8; j2++){
                const uint32_t vb = vbase + (uint32_t)((j2*8 + r)*AT_ROWV
                                                       + kk*32 + c4*4);
                uint32_t vh2[2], vl2[2];
                vh2[0] = lds32(vb);
                vh2[1] = lds32(vb + 16);
                vl2[0] = lds32(vb + AT_MV);
                vl2[1] = lds32(vb + AT_MV + 16);
                mma16816(o[j2], a_h, vh2);
                mma16816(o[j2], a_h, vl2);
                mma16816(o[j2], a_l, vh2);
            }
        }
        __syncthreads();
    }

    // ---- epilogue: write YH/YL bf16 hi/lo [M][768] ----
    const float inv0 = 1.f / l0, inv1 = 1.f / l1;
    const int bq = bh / H_, hh = bh % H_;
    const int t0 = qt*128 + w*16 + r;
    #pragma unroll
    for (int j2 = 0; j2 < 8; j2++){
        const int cc = hh*64 + j2*8 + c4*2;
        const float y0 = o[j2][0]*inv0, y1 = o[j2][1]*inv0;
        const float y2 = o[j2][2]*inv1, y3 = o[j2][3]*inv1;
        const size_t r0 = (size_t)(bq*T_ + t0    )*C_ + cc;
        const size_t r1 = (size_t)(bq*T_ + t0 + 8)*C_ + cc;
        *(uint32_t*)&g_YH[r0] = packbf(y0, y1);
        *(uint32_t*)&g_YL[r0] = packbf(y0 - bfhi(y0), y1 - bfhi(y1));
        *(uint32_t*)&g_YH[r1] = packbf(y2, y3);
        *(uint32_t*)&g_YL[r1] = packbf(y2 - bfhi(y2), y3 - bfhi(y3));
    }
}

// ---------------------------------------------------------------------------
extern "C" void kernel_launch(void* const* d_in, const int* in_sizes, int n_in,
                              void* d_out, int out_size)
{
    const float* x      = (const float*)d_in[0];
    const float* w_attn = (const float*)d_in[1];
    const float* b_attn = (const float*)d_in[2];
    const float* w_proj = (const float*)d_in[3];
    const float* b_proj = (const float*)d_in[4];
    float* out = (float*)d_out;

    cudaFuncSetAttribute(mma_gemm<1>, cudaFuncAttributeMaxDynamicSharedMemorySize, GEMM_SMEM);
    cudaFuncSetAttribute(mma_gemm<0>, cudaFuncAttributeMaxDynamicSharedMemorySize, GEMM_SMEM);
    cudaFuncSetAttribute(attn_tc, cudaFuncAttributeMaxDynamicSharedMemorySize, ATTN_SMEM);

    // 1) split x; transpose+split weights
    convert_split_x<<<(M_*C_/4 + 255)/256, 256>>>(x);
    transpose_split<0><<<dim3(3*C_/32, C_/32), dim3(32, 8)>>>(w_attn);
    transpose_split<1><<<dim3(C_/32,   C_/32), dim3(32, 8)>>>(w_proj);

    // 2) QKV projection -> bf16 hi/lo Q(scaled)/K/V(transposed)
    mma_gemm<1><<<dim3(3*C_/128, M_/128), 256, GEMM_SMEM>>>(b_attn, nullptr);

    // 3) tensor-core causal flash attention -> YH/YL
    attn_tc<<<dim3(T_/128, B_*H_), 256, ATTN_SMEM>>>();

    // 4) output projection -> d_out
    mma_gemm<0><<<dim3(C_/128, M_/128), 256, GEMM_SMEM>>>(b_proj, out);
}

// round 7
// speedup vs baseline: 2.4497x; 1.0856x over previous
#include <cuda_runtime.h>
#include <cuda_bf16.h>
#include <cstdint>

// Problem constants
#define B_  8
#define T_  1024
#define C_  768
#define H_  12
#define HS_ 64
#define M_  8192   // B*T

// ---------------------------------------------------------------------------
// Device-global scratch (no runtime allocation allowed)
// ---------------------------------------------------------------------------
__device__ __nv_bfloat16 g_XH[(size_t)M_*C_], g_XL[(size_t)M_*C_];
__device__ __nv_bfloat16 g_YH[(size_t)M_*C_], g_YL[(size_t)M_*C_];
__device__ __nv_bfloat16 g_WaH[(size_t)3*C_*C_], g_WaL[(size_t)3*C_*C_];
__device__ __nv_bfloat16 g_WpH[(size_t)C_*C_],   g_WpL[(size_t)C_*C_];

// Q/K: [B,H,T,hs] bf16 hi/lo (Q prescaled by 0.125). V: TRANSPOSED [B,H,hs,T].
__device__ __nv_bfloat16 g_Qh[B_*H_*T_*HS_], g_Ql[B_*H_*T_*HS_];
__device__ __nv_bfloat16 g_Kh[B_*H_*T_*HS_], g_Kl[B_*H_*T_*HS_];
__device__ __nv_bfloat16 g_Vh[B_*H_*T_*HS_], g_Vl[B_*H_*T_*HS_];

// ---------------------------------------------------------------------------
// Helpers (portable PTX only — compiles for plain sm_103 target)
// ---------------------------------------------------------------------------
__device__ __forceinline__ uint32_t smem_u32(const void* p){
    return (uint32_t)__cvta_generic_to_shared(p);
}
__device__ __forceinline__ void cpa16(uint32_t d, const void* s){
    asm volatile("cp.async.cg.shared.global [%0], [%1], 16;" :: "r"(d), "l"(s));
}
// ldmatrix x4: 4 8x8 bf16 matrices; lane l supplies row address of matrix l/8.
__device__ __forceinline__ void ldsm4(uint32_t& r0, uint32_t& r1,
                                      uint32_t& r2, uint32_t& r3, uint32_t a){
    asm volatile("ldmatrix.sync.aligned.m8n8.x4.shared.b16 {%0,%1,%2,%3}, [%4];"
                 : "=r"(r0), "=r"(r1), "=r"(r2), "=r"(r3) : "r"(a));
}
__device__ __forceinline__ void mma16816(float acc[4], const uint32_t a[4],
                                         const uint32_t b[2]){
    asm volatile(
        "mma.sync.aligned.m16n8k16.row.col.f32.bf16.bf16.f32 "
        "{%0,%1,%2,%3}, {%4,%5,%6,%7}, {%8,%9}, {%0,%1,%2,%3};"
        : "+f"(acc[0]), "+f"(acc[1]), "+f"(acc[2]), "+f"(acc[3])
        : "r"(a[0]), "r"(a[1]), "r"(a[2]), "r"(a[3]), "r"(b[0]), "r"(b[1]));
}
__device__ __forceinline__ uint32_t packbf(float x, float y){
    __nv_bfloat162 t = __float22bfloat162_rn(make_float2(x, y));
    return *(uint32_t*)&t;
}
__device__ __forceinline__ float bfhi(float x){
    return __bfloat162float(__float2bfloat16(x));
}

// per-lane ldmatrix row-offset helpers (byte offsets within a tile):
// A-operand order: m0=(r0-7,k0-7) m1=(r8-15,k0-7) m2=(r0-7,k8-15) m3=(r8-15,k8-15)
__device__ __forceinline__ uint32_t lm_offA(int lane, int rowb){
    return (uint32_t)(((lane & 7) + ((lane >> 3) & 1)*8) * rowb + (lane >> 4)*16);
}
// B-operand order: m0=(j,k0-7) m1=(j,k8-15) m2=(j+1,k0-7) m3=(j+1,k8-15)
__device__ __forceinline__ uint32_t lm_offB(int lane, int rowb){
    return (uint32_t)(((lane & 7) + (lane >> 4)*8) * rowb + ((lane >> 3) & 1)*16);
}

// ---------------------------------------------------------------------------
// Pre-pass: split x fp32 -> bf16 hi/lo
// ---------------------------------------------------------------------------
__global__ void convert_split_x(const float* __restrict__ src)
{
    const int i = blockIdx.x * blockDim.x + threadIdx.x;   // float4 index
    const int n4 = (M_*C_) / 4;
    if (i >= n4) return;
    const float4 v = ((const float4*)src)[i];
    const float h0 = bfhi(v.x), h1 = bfhi(v.y), h2 = bfhi(v.z), h3 = bfhi(v.w);
    ((uint32_t*)g_XH)[i*2    ] = packbf(v.x, v.y);
    ((uint32_t*)g_XH)[i*2 + 1] = packbf(v.z, v.w);
    ((uint32_t*)g_XL)[i*2    ] = packbf(v.x - h0, v.y - h1);
    ((uint32_t*)g_XL)[i*2 + 1] = packbf(v.z - h2, v.w - h3);
}

// ---------------------------------------------------------------------------
// Pre-pass: transpose + split weights -> [N][768] bf16 hi/lo (K-major)
// ---------------------------------------------------------------------------
template<int WHICH>
__global__ void transpose_split(const float* __restrict__ w)
{
    constexpr int N = (WHICH == 0) ? 3*C_ : C_;
    __nv_bfloat16* Hh = (WHICH == 0) ? g_WaH : g_WpH;
    __nv_bfloat16* Ll = (WHICH == 0) ? g_WaL : g_WpL;

    __shared__ float tile[32][33];
    const int nb = blockIdx.x * 32;
    const int kb = blockIdx.y * 32;
    const int tx = threadIdx.x;   // 0..31
    const int ty = threadIdx.y;   // 0..7

    #pragma unroll
    for (int i = ty; i < 32; i += 8)
        tile[i][tx] = w[(size_t)(kb + i) * N + nb + tx];
    __syncthreads();

    #pragma unroll
    for (int i = ty; i < 32; i += 8){
        const float v = tile[tx][i];            // = w[kb+tx][nb+i]
        const __nv_bfloat16 h = __float2bfloat16(v);
        const __nv_bfloat16 l = __float2bfloat16(v - __bfloat162float(h));
        const size_t o = (size_t)(nb + i) * C_ + kb + tx;
        Hh[o] = h;
        Ll[o] = l;
    }
}

// ---------------------------------------------------------------------------
// Tensor-core GEMM (bf16 hi/lo, 3-pass compensation), ldmatrix fragment loads.
// MODE 1: A=XH/XL, B=WaH/WaL -> scatter bf16 hi/lo into Qh/Ql,Kh/Kl,Vh/Vl(T)
// MODE 0: A=YH/YL, B=WpH/WpL -> fp32 Cout (d_out)
// ---------------------------------------------------------------------------
constexpr int ROWB   = 80;           // bytes per smem row (32 bf16 + pad)
constexpr int MATB   = 128 * ROWB;   // 10240 B per matrix tile
constexpr int STAGEB = 4 * MATB;     // 40960 B per stage (AH,AL,BH,BL)
constexpr int GEMM_SMEM = 2 * STAGEB;// 81920 B

template<int MODE>
__global__ __launch_bounds__(256, 2)
void mma_gemm(const float* __restrict__ bias, float* __restrict__ Cout)
{
    extern __shared__ __align__(128) uint8_t smem[];

    const __nv_bfloat16* AH = (MODE == 1) ? g_XH : g_YH;
    const __nv_bfloat16* AL = (MODE == 1) ? g_XL : g_YL;
    const __nv_bfloat16* BH = (MODE == 1) ? g_WaH : g_WpH;
    const __nv_bfloat16* BL = (MODE == 1) ? g_WaL : g_WpL;

    const int tid  = threadIdx.x;
    const int lane = tid & 31;
    const int warp = tid >> 5;
    const int wm   = warp & 1;
    const int wn   = warp >> 1;
    const int bc   = blockIdx.x;
    const int br   = blockIdx.y;

    const uint32_t sb = smem_u32(smem);

    auto load_stage = [&](int kt, int s){
        const uint32_t st = sb + (uint32_t)s * STAGEB;
        #pragma unroll
        for (int j = 0; j < 2; j++){
            const int ch  = tid + j*256;
            const int row = ch >> 2;
            const int cc  = ch & 3;
            const uint32_t so = (uint32_t)(row*ROWB + cc*16);
            const size_t ga = (size_t)(br*128 + row) * C_ + kt*32 + cc*8;
            const size_t gb = (size_t)(bc*128 + row) * C_ + kt*32 + cc*8;
            cpa16(st            + so, AH + ga);
            cpa16(st +   MATB   + so, AL + ga);
            cpa16(st + 2*MATB   + so, BH + gb);
            cpa16(st + 3*MATB   + so, BL + gb);
        }
        asm volatile("cp.async.commit_group;");
    };

    float acc[4][4][4];
    #pragma unroll
    for (int i = 0; i < 4; i++)
        #pragma unroll
        for (int j = 0; j < 4; j++)
            #pragma unroll
            for (int q = 0; q < 4; q++) acc[i][j][q] = 0.f;

    constexpr int NK = C_ / 32;    // 24

    load_stage(0, 0);
    asm volatile("cp.async.wait_group 0;");
    __syncthreads();

    // per-lane ldmatrix offsets
    const uint32_t offA = lm_offA(lane, ROWB) + (uint32_t)(wm*64)*ROWB;
    const uint32_t offB = lm_offB(lane, ROWB) + (uint32_t)(wn*32)*ROWB + 2*MATB;

    for (int kt = 0; kt < NK; kt++){
        const int cur = kt & 1;
        if (kt + 1 < NK) load_stage(kt + 1, cur ^ 1);

        const uint32_t st = sb + (uint32_t)cur * STAGEB;

        #pragma unroll
        for (int kk = 0; kk < 2; kk++){
            // B fragments for this kk: 2 LDSM.x4 per hi/lo (j pairs)
            uint32_t bh[4][2], bl[4][2];
            #pragma unroll
            for (int jp = 0; jp < 2; jp++){
                const uint32_t ab = st + offB + (uint32_t)(jp*16)*ROWB + kk*32;
                ldsm4(bh[2*jp][0], bh[2*jp][1], bh[2*jp+1][0], bh[2*jp+1][1], ab);
                ldsm4(bl[2*jp][0], bl[2*jp][1], bl[2*jp+1][0], bl[2*jp+1][1],
                      ab + MATB);
            }
            // stream A rows: 2 LDSM.x4 per i
            #pragma unroll
            for (int i = 0; i < 4; i++){
                const uint32_t aa = st + offA + (uint32_t)(i*16)*ROWB + kk*32;
                uint32_t ah[4], al[4];
                ldsm4(ah[0], ah[1], ah[2], ah[3], aa);
                ldsm4(al[0], al[1], al[2], al[3], aa + MATB);
                #pragma unroll
                for (int j = 0; j < 4; j++){
                    mma16816(acc[i][j], ah, bh[j]);
                    mma16816(acc[i][j], ah, bl[j]);
                    mma16816(acc[i][j], al, bh[j]);
                }
            }
        }

        if (kt + 1 < NK) asm volatile("cp.async.wait_group 0;");
        __syncthreads();
    }

    const int r  = lane >> 2;
    const int c4 = lane & 3;

    // Epilogue
    #pragma unroll
    for (int j = 0; j < 4; j++){
        const int col = bc*128 + wn*32 + j*8 + c4*2;
        const float2 bv = *(const float2*)&bias[col];
        if (MODE == 0){
            #pragma unroll
            for (int i = 0; i < 4; i++){
                const int row0 = br*128 + wm*64 + i*16 + r;
                float2 v0 = make_float2(acc[i][j][0] + bv.x, acc[i][j][1] + bv.y);
                float2 v1 = make_float2(acc[i][j][2] + bv.x, acc[i][j][3] + bv.y);
                *(float2*)&Cout[(size_t)row0     * C_ + col] = v0;
                *(float2*)&Cout[(size_t)(row0+8) * C_ + col] = v1;
            }
        } else {
            const int which = col / C_;
            const int rem   = col - which * C_;
            const int hh = rem >> 6;
            const int dd = rem & 63;
            #pragma unroll
            for (int i = 0; i < 4; i++){
                const int row0 = br*128 + wm*64 + i*16 + r;
                const int b0i = row0 >> 10, t0i = row0 & 1023;
                const int row1 = row0 + 8;
                const int b1i = row1 >> 10, t1i = row1 & 1023;
                float v00 = acc[i][j][0] + bv.x, v01 = acc[i][j][1] + bv.y;
                float v10 = acc[i][j][2] + bv.x, v11 = acc[i][j][3] + bv.y;
                if (which == 0){ v00*=0.125f; v01*=0.125f; v10*=0.125f; v11*=0.125f; }
                if (which < 2){
                    __nv_bfloat16* DH = (which == 0) ? g_Qh : g_Kh;
                    __nv_bfloat16* DL = (which == 0) ? g_Ql : g_Kl;
                    const size_t o0 = ((size_t)(b0i*H_ + hh)*T_ + t0i)*HS_ + dd;
                    const size_t o1 = ((size_t)(b1i*H_ + hh)*T_ + t1i)*HS_ + dd;
                    *(uint32_t*)&DH[o0] = packbf(v00, v01);
                    *(uint32_t*)&DL[o0] = packbf(v00 - bfhi(v00), v01 - bfhi(v01));
                    *(uint32_t*)&DH[o1] = packbf(v10, v11);
                    *(uint32_t*)&DL[o1] = packbf(v10 - bfhi(v10), v11 - bfhi(v11));
                } else {
                    // V transposed: [B,H,d,T]
                    const size_t vb0 = ((size_t)(b0i*H_ + hh)*HS_ + dd)*T_;
                    const size_t vb1 = ((size_t)(b1i*H_ + hh)*HS_ + dd)*T_;
                    g_Vh[vb0      + t0i] = __float2bfloat16(v00);
                    g_Vh[vb0 + T_ + t0i] = __float2bfloat16(v01);
                    g_Vh[vb1      + t1i] = __float2bfloat16(v10);
                    g_Vh[vb1 + T_ + t1i] = __float2bfloat16(v11);
                    g_Vl[vb0      + t0i] = __float2bfloat16(v00 - bfhi(v00));
                    g_Vl[vb0 + T_ + t0i] = __float2bfloat16(v01 - bfhi(v01));
                    g_Vl[vb1      + t1i] = __float2bfloat16(v10 - bfhi(v10));
                    g_Vl[vb1 + T_ + t1i] = __float2bfloat16(v11 - bfhi(v11));
                }
            }
        }
    }
}

// ---------------------------------------------------------------------------
// Tensor-core causal flash attention, ldmatrix fragment loads.
// ---------------------------------------------------------------------------
constexpr int AT_ROWK = 144;
constexpr int AT_ROWV = 272;
constexpr int AT_MK   = 128 * AT_ROWK;   // 18432
constexpr int AT_MV   = 64  * AT_ROWV;   // 17408
constexpr int AT_Q    = 2 * AT_MK;       // 36864
constexpr int AT_STAGE= 2*AT_MK + 2*AT_MV;  // 71680
constexpr int ATTN_SMEM = AT_Q + 2*AT_STAGE;// 180224

__global__ __launch_bounds__(256, 1)
void attn_tc()
{
    extern __shared__ __align__(128) uint8_t smx[];
    const uint32_t sb = smem_u32(smx);

    const int qt  = blockIdx.x;    // 0..7
    const int bh  = blockIdx.y;    // 0..95
    const int tid = threadIdx.x;
    const int lane = tid & 31;
    const int w    = tid >> 5;
    const int r    = lane >> 2;
    const int c4   = lane & 3;

    // ---- async loads ----
    const size_t qoff = ((size_t)bh*T_ + qt*128) * HS_;
    #pragma unroll
    for (int j = 0; j < 4; j++){
        const int ch = tid + 256*j;           // 0..1023
        const int row = ch >> 3, c = ch & 7;
        const uint32_t so = sb + (uint32_t)(row*AT_ROWK + c*16);
        const size_t g = qoff + (size_t)row*HS_ + c*8;
        cpa16(so,         g_Qh + g);
        cpa16(so + AT_MK, g_Ql + g);
    }

    auto load_kv = [&](int kt, int s){
        const uint32_t st = sb + AT_Q + (uint32_t)s * AT_STAGE;
        const size_t koff = ((size_t)bh*T_ + kt*128) * HS_;
        #pragma unroll
        for (int j = 0; j < 4; j++){
            const int ch = tid + 256*j;
            const int row = ch >> 3, c = ch & 7;
            const uint32_t so = st + (uint32_t)(row*AT_ROWK + c*16);
            const size_t g = koff + (size_t)row*HS_ + c*8;
            cpa16(so,         g_Kh + g);
            cpa16(so + AT_MK, g_Kl + g);
        }
        const size_t voff = (size_t)bh*HS_*T_ + kt*128;
        #pragma unroll
        for (int j = 0; j < 4; j++){
            const int ch = tid + 256*j;
            const int row = ch >> 4, c = ch & 15;   // row 0..63
            const uint32_t so = st + 2*AT_MK + (uint32_t)(row*AT_ROWV + c*16);
            const size_t g = voff + (size_t)row*T_ + c*8;
            cpa16(so,         g_Vh + g);
            cpa16(so + AT_MV, g_Vl + g);
        }
        asm volatile("cp.async.commit_group;");
    };

    load_kv(0, 0);   // group 0 = Q + stage0

    float m0 = -1e30f, m1 = -1e30f, l0 = 0.f, l1 = 0.f;
    float o[8][4];
    #pragma unroll
    for (int j2 = 0; j2 < 8; j2++)
        #pragma unroll
        for (int q = 0; q < 4; q++) o[j2][q] = 0.f;

    // per-lane ldmatrix offsets
    const uint32_t offQ = lm_offA(lane, AT_ROWK) + (uint32_t)(w*16)*AT_ROWK;
    const uint32_t offK = lm_offB(lane, AT_ROWK);
    const uint32_t offV = lm_offB(lane, AT_ROWV);

    for (int kt = 0; kt <= qt; kt++){
        if (kt < qt){
            load_kv(kt + 1, (kt + 1) & 1);
            asm volatile("cp.async.wait_group 1;");
        } else {
            asm volatile("cp.async.wait_group 0;");
        }
        __syncthreads();

        const uint32_t st = sb + AT_Q + (uint32_t)(kt & 1) * AT_STAGE;

        // ---- S = Q @ K^T (3-pass hi/lo) ----
        float s[16][4];
        #pragma unroll
        for (int j = 0; j < 16; j++){
            s[j][0] = s[j][1] = s[j][2] = s[j][3] = 0.f;
        }
        #pragma unroll
        for (int kk = 0; kk < 4; kk++){
            uint32_t qh[4], ql[4];
            {
                const uint32_t qa = sb + offQ + kk*32;
                ldsm4(qh[0], qh[1], qh[2], qh[3], qa);
                ldsm4(ql[0], ql[1], ql[2], ql[3], qa + AT_MK);
            }
            #pragma unroll
            for (int jp = 0; jp < 8; jp++){
                const uint32_t ka = st + offK + (uint32_t)(jp*16)*AT_ROWK + kk*32;
                uint32_t kh[2][2], kl[2][2];
                ldsm4(kh[0][0], kh[0][1], kh[1][0], kh[1][1], ka);
                ldsm4(kl[0][0], kl[0][1], kl[1][0], kl[1][1], ka + AT_MK);
                mma16816(s[2*jp  ], qh, kh[0]);
                mma16816(s[2*jp  ], qh, kl[0]);
                mma16816(s[2*jp  ], ql, kh[0]);
                mma16816(s[2*jp+1], qh, kh[1]);
                mma16816(s[2*jp+1], qh, kl[1]);
                mma16816(s[2*jp+1], ql, kh[1]);
            }
        }

        // ---- causal mask on diagonal tile ----
        if (kt == qt){
            const int row0 = w*16 + r;
            #pragma unroll
            for (int j = 0; j < 16; j++){
                const int col0 = j*8 + c4*2;
                if (col0     > row0    ) s[j][0] = -1e30f;
                if (col0 + 1 > row0    ) s[j][1] = -1e30f;
                if (col0     > row0 + 8) s[j][2] = -1e30f;
                if (col0 + 1 > row0 + 8) s[j][3] = -1e30f;
            }
        }

        // ---- online softmax ----
        float rm0 = -1e30f, rm1 = -1e30f;
        #pragma unroll
        for (int j = 0; j < 16; j++){
            rm0 = fmaxf(rm0, fmaxf(s[j][0], s[j][1]));
            rm1 = fmaxf(rm1, fmaxf(s[j][2], s[j][3]));
        }
        rm0 = fmaxf(rm0, __shfl_xor_sync(0xffffffffu, rm0, 1));
        rm0 = fmaxf(rm0, __shfl_xor_sync(0xffffffffu, rm0, 2));
        rm1 = fmaxf(rm1, __shfl_xor_sync(0xffffffffu, rm1, 1));
        rm1 = fmaxf(rm1, __shfl_xor_sync(0xffffffffu, rm1, 2));
        const float mn0 = fmaxf(m0, rm0), mn1 = fmaxf(m1, rm1);
        const float a0 = __expf(m0 - mn0), a1 = __expf(m1 - mn1);
        m0 = mn0; m1 = mn1;
        float rs0 = 0.f, rs1 = 0.f;
        #pragma unroll
        for (int j = 0; j < 16; j++){
            s[j][0] = __expf(s[j][0] - mn0);
            s[j][1] = __expf(s[j][1] - mn0);
            s[j][2] = __expf(s[j][2] - mn1);
            s[j][3] = __expf(s[j][3] - mn1);
            rs0 += s[j][0] + s[j][1];
            rs1 += s[j][2] + s[j][3];
        }
        rs0 += __shfl_xor_sync(0xffffffffu, rs0, 1);
        rs0 += __shfl_xor_sync(0xffffffffu, rs0, 2);
        rs1 += __shfl_xor_sync(0xffffffffu, rs1, 1);
        rs1 += __shfl_xor_sync(0xffffffffu, rs1, 2);
        l0 = l0*a0 + rs0;
        l1 = l1*a1 + rs1;
        #pragma unroll
        for (int j2 = 0; j2 < 8; j2++){
            o[j2][0] *= a0; o[j2][1] *= a0;
            o[j2][2] *= a1; o[j2][3] *= a1;
        }

        // ---- O += P @ V (3-pass: Ph*Vh + Ph*Vl + Pl*Vh) ----
        const uint32_t vbase = st + 2*AT_MK;
        #pragma unroll
        for (int kk = 0; kk < 8; kk++){
            float ph[8], pl[8];
            #pragma unroll
            for (int e = 0; e < 4; e++){
                ph[e]   = bfhi(s[2*kk  ][e]);  pl[e]   = s[2*kk  ][e] - ph[e];
                ph[4+e] = bfhi(s[2*kk+1][e]);  pl[4+e] = s[2*kk+1][e] - ph[4+e];
            }
            uint32_t a_h[4], a_l[4];
            a_h[0] = packbf(ph[0], ph[1]);  a_h[1] = packbf(ph[2], ph[3]);
            a_h[2] = packbf(ph[4], ph[5]);  a_h[3] = packbf(ph[6], ph[7]);
            a_l[0] = packbf(pl[0], pl[1]);  a_l[1] = packbf(pl[2], pl[3]);
            a_l[2] = packbf(pl[4], pl[5]);  a_l[3] = packbf(pl[6], pl[7]);
            #pragma unroll
            for (int jp = 0; jp < 4; jp++){
                const uint32_t va = vbase + offV + (uint32_t)(jp*16)*AT_ROWV
                                  + kk*32;
                uint32_t vh[2][2], vl[2][2];
                ldsm4(vh[0][0], vh[0][1], vh[1][0], vh[1][1], va);
                ldsm4(vl[0][0], vl[0][1], vl[1][0], vl[1][1], va + AT_MV);
                mma16816(o[2*jp  ], a_h, vh[0]);
                mma16816(o[2*jp  ], a_h, vl[0]);
                mma16816(o[2*jp  ], a_l, vh[0]);
                mma16816(o[2*jp+1], a_h, vh[1]);
                mma16816(o[2*jp+1], a_h, vl[1]);
                mma16816(o[2*jp+1], a_l, vh[1]);
            }
        }
        __syncthreads();
    }

    // ---- epilogue: write YH/YL bf16 hi/lo [M][768] ----
    const float inv0 = 1.f / l0, inv1 = 1.f / l1;
    const int bq = bh / H_, hh = bh % H_;
    const int t0 = qt*128 + w*16 + r;
    #pragma unroll
    for (int j2 = 0; j2 < 8; j2++){
        const int cc = hh*64 + j2*8 + c4*2;
        const float y0 = o[j2][0]*inv0, y1 = o[j2][1]*inv0;
        const float y2 = o[j2][2]*inv1, y3 = o[j2][3]*inv1;
        const size_t r0 = (size_t)(bq*T_ + t0    )*C_ + cc;
        const size_t r1 = (size_t)(bq*T_ + t0 + 8)*C_ + cc;
        *(uint32_t*)&g_YH[r0] = packbf(y0, y1);
        *(uint32_t*)&g_YL[r0] = packbf(y0 - bfhi(y0), y1 - bfhi(y1));
        *(uint32_t*)&g_YH[r1] = packbf(y2, y3);
        *(uint32_t*)&g_YL[r1] = packbf(y2 - bfhi(y2), y3 - bfhi(y3));
    }
}

// ---------------------------------------------------------------------------
extern "C" void kernel_launch(void* const* d_in, const int* in_sizes, int n_in,
                              void* d_out, int out_size)
{
    const float* x      = (const float*)d_in[0];
    const float* w_attn = (const float*)d_in[1];
    const float* b_attn = (const float*)d_in[2];
    const float* w_proj = (const float*)d_in[3];
    const float* b_proj = (const float*)d_in[4];
    float* out = (float*)d_out;

    cudaFuncSetAttribute(mma_gemm<1>, cudaFuncAttributeMaxDynamicSharedMemorySize, GEMM_SMEM);
    cudaFuncSetAttribute(mma_gemm<0>, cudaFuncAttributeMaxDynamicSharedMemorySize, GEMM_SMEM);
    cudaFuncSetAttribute(attn_tc, cudaFuncAttributeMaxDynamicSharedMemorySize, ATTN_SMEM);

    // 1) split x; transpose+split weights
    convert_split_x<<<(M_*C_/4 + 255)/256, 256>>>(x);
    transpose_split<0><<<dim3(3*C_/32, C_/32), dim3(32, 8)>>>(w_attn);
    transpose_split<1><<<dim3(C_/32,   C_/32), dim3(32, 8)>>>(w_proj);

    // 2) QKV projection -> bf16 hi/lo Q(scaled)/K/V(transposed)
    mma_gemm<1><<<dim3(3*C_/128, M_/128), 256, GEMM_SMEM>>>(b_attn, nullptr);

    // 3) tensor-core causal flash attention -> YH/YL
    attn_tc<<<dim3(T_/128, B_*H_), 256, ATTN_SMEM>>>();

    // 4) output projection -> d_out
    mma_gemm<0><<<dim3(C_/128, M_/128), 256, GEMM_SMEM>>>(b_proj, out);
}